// round 1
// baseline (speedup 1.0000x reference)
#include <cuda_runtime.h>
#include <math.h>

#define BB 16
#define NN 1024
#define DIMM 512
#define HH 8
#define HD 64
#define QKV_N 1536
#define M_ROWS (BB*NN)          // 16384
#define QSCALE 0.125f           // HEAD_DIM^-0.5
#define PI_F 3.14159265358979323846f

// ---------------- scratch (device globals: no allocation allowed) ----------------
__device__ float g_qkv[(size_t)M_ROWS * QKV_N];   // (B*N, 1536)  ~100MB
__device__ float g_ao[(size_t)M_ROWS * DIMM];     // attention out (B*N, 512)
__device__ float g_xmean[M_ROWS];                 // mean over DIM
__device__ float g_xavg[BB * DIMM];               // mean over N
__device__ float g_f[BB * NN];                    // normalized DCT features
__device__ float g_coef[BB * NN];                 // s*f_n / max(s*f_n*F, 1e-5)

// ---------------- 128x128x8 SGEMM with bias ----------------
// C = A(MxK) @ B(KxNc) + bias.  Aarg==nullptr -> g_ao ; Carg==nullptr -> g_qkv
__global__ __launch_bounds__(256) void sgemm_bias(
    const float* Aarg, const float* __restrict__ Bm,
    const float* __restrict__ bias, float* Carg, int Nc, int K)
{
    const float* A = Aarg ? Aarg : g_ao;
    float*       C = Carg ? Carg : g_qkv;

    __shared__ float As[8][128];
    __shared__ float Bs[8][128];

    int tid = threadIdx.x;
    int bx = blockIdx.x, by = blockIdx.y;
    int tx = tid & 15, ty = tid >> 4;

    float acc[8][8];
#pragma unroll
    for (int i = 0; i < 8; i++)
#pragma unroll
        for (int j = 0; j < 8; j++) acc[i][j] = 0.f;

    int arow = tid >> 1, acol = (tid & 1) << 2;
    const float* Aptr = A + (size_t)(by * 128 + arow) * K + acol;
    int brow = tid >> 5, bcol = (tid & 31) << 2;
    const float* Bptr = Bm + (size_t)brow * Nc + bx * 128 + bcol;

    for (int kt = 0; kt < K; kt += 8) {
        float4 av = *(const float4*)(Aptr + kt);
        float4 bv = *(const float4*)(Bptr + (size_t)kt * Nc);
        As[acol + 0][arow] = av.x;
        As[acol + 1][arow] = av.y;
        As[acol + 2][arow] = av.z;
        As[acol + 3][arow] = av.w;
        *(float4*)&Bs[brow][bcol] = bv;
        __syncthreads();
#pragma unroll
        for (int kk = 0; kk < 8; kk++) {
            float a[8], b[8];
            *(float4*)&a[0] = *(const float4*)&As[kk][ty * 4];
            *(float4*)&a[4] = *(const float4*)&As[kk][64 + ty * 4];
            *(float4*)&b[0] = *(const float4*)&Bs[kk][tx * 4];
            *(float4*)&b[4] = *(const float4*)&Bs[kk][64 + tx * 4];
#pragma unroll
            for (int i = 0; i < 8; i++)
#pragma unroll
                for (int j = 0; j < 8; j++) acc[i][j] += a[i] * b[j];
        }
        __syncthreads();
    }

    float bb[8];
#pragma unroll
    for (int j = 0; j < 4; j++) {
        bb[j]     = bias[bx * 128 + tx * 4 + j];
        bb[4 + j] = bias[bx * 128 + 64 + tx * 4 + j];
    }
#pragma unroll
    for (int ih = 0; ih < 2; ih++) {
#pragma unroll
        for (int i = 0; i < 4; i++) {
            int row = by * 128 + ih * 64 + ty * 4 + i;
            float4 v0, v1;
            v0.x = acc[ih * 4 + i][0] + bb[0];
            v0.y = acc[ih * 4 + i][1] + bb[1];
            v0.z = acc[ih * 4 + i][2] + bb[2];
            v0.w = acc[ih * 4 + i][3] + bb[3];
            v1.x = acc[ih * 4 + i][4] + bb[4];
            v1.y = acc[ih * 4 + i][5] + bb[5];
            v1.z = acc[ih * 4 + i][6] + bb[6];
            v1.w = acc[ih * 4 + i][7] + bb[7];
            *(float4*)&C[(size_t)row * Nc + bx * 128 + tx * 4] = v0;
            *(float4*)&C[(size_t)row * Nc + bx * 128 + 64 + tx * 4] = v1;
        }
    }
}

// ---------------- per-row mean over DIM ----------------
__global__ void rowmean_kernel(const float* __restrict__ x)
{
    int row = blockIdx.x * 8 + (threadIdx.x >> 5);
    int lane = threadIdx.x & 31;
    const float* p = x + (size_t)row * DIMM;
    float s = 0.f;
#pragma unroll
    for (int c = lane * 4; c < DIMM; c += 128) {
        float4 v = *(const float4*)(p + c);
        s += (v.x + v.y) + (v.z + v.w);
    }
#pragma unroll
    for (int o = 16; o; o >>= 1) s += __shfl_xor_sync(0xffffffffu, s, o);
    if (lane == 0) g_xmean[row] = s * (1.f / DIMM);
}

// ---------------- per-column mean over N ----------------
__global__ void colmean_kernel(const float* __restrict__ x)
{
    int b = blockIdx.x;
    int c = blockIdx.y * 128 + threadIdx.x;
    const float* p = x + (size_t)b * NN * DIMM + c;
    float s0 = 0.f, s1 = 0.f, s2 = 0.f, s3 = 0.f;
    for (int n = 0; n < NN; n += 4) {
        s0 += p[(n + 0) * DIMM];
        s1 += p[(n + 1) * DIMM];
        s2 += p[(n + 2) * DIMM];
        s3 += p[(n + 3) * DIMM];
    }
    g_xavg[b * DIMM + c] = (s0 + s1 + s2 + s3) * (1.f / NN);
}

// ---------------- per-batch DCT features + head-weight MLP -> f, coef ----------------
__global__ void prep_kernel(const float* __restrict__ h1_w, const float* __restrict__ h1_b,
                            const float* __restrict__ h2_w, const float* __restrict__ h2_b)
{
    int b = blockIdx.x, tid = threadIdx.x;   // 256 threads
    __shared__ float D[32][33], Am[32][33], T[32][33];
    __shared__ float fbuf[1024];
    __shared__ float xa[512], hid[128], red[256];
    __shared__ float s_norm, s_F, s_s2;

    // DCT matrix
    for (int idx = tid; idx < 1024; idx += 256) {
        int k = idx >> 5, n = idx & 31;
        float v;
        if (k == 0) v = sqrtf(1.f / 32.f);
        else v = sqrtf(2.f / 32.f) * cosf(PI_F * (2.f * n + 1.f) * (float)k / 64.f);
        D[k][n] = v;
    }
    for (int idx = tid; idx < 1024; idx += 256)
        Am[idx >> 5][idx & 31] = g_xmean[b * NN + idx];
    xa[tid]       = g_xavg[b * DIMM + tid];
    xa[tid + 256] = g_xavg[b * DIMM + tid + 256];
    __syncthreads();

    // T = D @ A
    for (int idx = tid; idx < 1024; idx += 256) {
        int k = idx >> 5, n = idx & 31;
        float s = 0.f;
#pragma unroll
        for (int m = 0; m < 32; m++) s += D[k][m] * Am[m][n];
        T[k][n] = s;
    }
    __syncthreads();

    // dct2 = T @ D^T, clip, sum of squares
    float myv[4];
    float sq = 0.f;
#pragma unroll
    for (int u = 0; u < 4; u++) {
        int idx = tid + u * 256;
        int k = idx >> 5, l = idx & 31;
        float s = 0.f;
#pragma unroll
        for (int n = 0; n < 32; n++) s += T[k][n] * D[l][n];
        s = fminf(fmaxf(s, -10.f), 10.f);
        myv[u] = s;
        sq += s * s;
    }
    red[tid] = sq;
    __syncthreads();
    for (int o = 128; o; o >>= 1) { if (tid < o) red[tid] += red[tid + o]; __syncthreads(); }
    if (tid == 0) s_norm = sqrtf(red[0]) + 1e-5f;
    __syncthreads();

    float inv = 1.f / s_norm;
    float sumf = 0.f;
#pragma unroll
    for (int u = 0; u < 4; u++) {
        myv[u] *= inv;
        fbuf[tid + u * 256] = myv[u];
        sumf += myv[u];
    }
    red[tid] = sumf;
    __syncthreads();
    for (int o = 128; o; o >>= 1) { if (tid < o) red[tid] += red[tid + o]; __syncthreads(); }
    if (tid == 0) s_F = red[0];
    __syncthreads();

    // head MLP: relu(xa @ h1_w + h1_b) @ h2_w + h2_b ; s2 = sum of squares
    if (tid < 128) {
        float s = h1_b[tid];
        for (int c = 0; c < 512; c++) s += xa[c] * h1_w[c * 128 + tid];
        hid[tid] = fmaxf(s, 0.f);
    }
    __syncthreads();
    if (tid < 8) {
        float s = h2_b[tid];
        for (int j = 0; j < 128; j++) s += hid[j] * h2_w[j * 8 + tid];
        red[tid] = s * s;
    }
    __syncthreads();
    if (tid == 0)
        s_s2 = red[0] + red[1] + red[2] + red[3] + red[4] + red[5] + red[6] + red[7];
    __syncthreads();

    float s2 = s_s2, F = s_F;
#pragma unroll
    for (int u = 0; u < 4; u++) {
        int idx = tid + u * 256;
        float fv = fbuf[idx];
        g_f[b * NN + idx] = fv;
        float num = s2 * fv;
        g_coef[b * NN + idx] = num / fmaxf(num * F, 1e-5f);
    }
}

// ---------------- fused flash-attention (fp32, online softmax, rank-1 freq mix) ----------------
// grid (N/64, B*H), block 128 (tx 0..15 -> 4 d/m cols, ty 0..7 -> 8 q rows)
__global__ __launch_bounds__(128) void attn_kernel(const float* __restrict__ freq_w)
{
    __shared__ float Qs[64 * 64];   // [d][n]  (transposed)
    __shared__ float KPs[64 * 64];  // K phase: [d][m] ; P phase: [n][m]
    __shared__ float Vs[64 * 64];   // [m][d]

    int qt = blockIdx.x;            // 0..15
    int bh = blockIdx.y;            // 0..127
    int b = bh >> 3, h = bh & 7;
    int tid = threadIdx.x;
    int tx = tid & 15, ty = tid >> 4;

    float aw = 1.f / (1.f + __expf(-freq_w[0]));
    float one_aw = 1.f - aw;

    // load Q tile transposed (scaled)
    {
        int n = tid >> 1, d0 = (tid & 1) * 32;
        const float* src = g_qkv + (size_t)(b * NN + qt * 64 + n) * QKV_N + h * HD + d0;
#pragma unroll
        for (int u = 0; u < 8; u++) {
            float4 v = *(const float4*)(src + 4 * u);
            int d = d0 + 4 * u;
            Qs[(d + 0) * 64 + n] = v.x * QSCALE;
            Qs[(d + 1) * 64 + n] = v.y * QSCALE;
            Qs[(d + 2) * 64 + n] = v.z * QSCALE;
            Qs[(d + 3) * 64 + n] = v.w * QSCALE;
        }
    }
    float coefr[8];
#pragma unroll
    for (int i = 0; i < 8; i++) coefr[i] = g_coef[b * NN + qt * 64 + ty * 8 + i];

    float mrow[8], lrow[8], o[8][4];
#pragma unroll
    for (int i = 0; i < 8; i++) {
        mrow[i] = -1e30f; lrow[i] = 0.f;
#pragma unroll
        for (int j = 0; j < 4; j++) o[i][j] = 0.f;
    }

    for (int kt = 0; kt < 16; kt++) {
        __syncthreads();   // previous P/V consumers done
        {
            int m = tid >> 1, d0 = (tid & 1) * 32;
            const float* ksrc = g_qkv + (size_t)(b * NN + kt * 64 + m) * QKV_N + 512 + h * HD + d0;
            const float* vsrc = ksrc + 512;
#pragma unroll
            for (int u = 0; u < 8; u++) {
                float4 kv = *(const float4*)(ksrc + 4 * u);
                int d = d0 + 4 * u;
                KPs[(d + 0) * 64 + m] = kv.x;
                KPs[(d + 1) * 64 + m] = kv.y;
                KPs[(d + 2) * 64 + m] = kv.z;
                KPs[(d + 3) * 64 + m] = kv.w;
                float4 vv = *(const float4*)(vsrc + 4 * u);
                *(float4*)&Vs[m * 64 + d] = vv;
            }
        }
        __syncthreads();

        // S = (Q*scale) K^T  (8x4 per thread)
        float sv[8][4];
#pragma unroll
        for (int i = 0; i < 8; i++)
#pragma unroll
            for (int j = 0; j < 4; j++) sv[i][j] = 0.f;
#pragma unroll 8
        for (int kk = 0; kk < 64; kk++) {
            float a[8], bf[4];
            *(float4*)&a[0] = *(const float4*)&Qs[kk * 64 + ty * 8];
            *(float4*)&a[4] = *(const float4*)&Qs[kk * 64 + ty * 8 + 4];
            *(float4*)&bf[0] = *(const float4*)&KPs[kk * 64 + tx * 4];
#pragma unroll
            for (int i = 0; i < 8; i++)
#pragma unroll
                for (int j = 0; j < 4; j++) sv[i][j] += a[i] * bf[j];
        }

        // mix in rank-1 frequency attention
        float fm[4];
#pragma unroll
        for (int j = 0; j < 4; j++) fm[j] = __ldg(&g_f[b * NN + kt * 64 + tx * 4 + j]);
#pragma unroll
        for (int i = 0; i < 8; i++)
#pragma unroll
            for (int j = 0; j < 4; j++) {
                float fa = coefr[i] * fm[j];
                fa = fminf(fmaxf(fa, 0.f), 1.f);
                sv[i][j] = one_aw * sv[i][j] + aw * fa;
            }

        // online softmax update
#pragma unroll
        for (int i = 0; i < 8; i++) {
            float t = fmaxf(fmaxf(sv[i][0], sv[i][1]), fmaxf(sv[i][2], sv[i][3]));
#pragma unroll
            for (int off = 1; off < 16; off <<= 1)
                t = fmaxf(t, __shfl_xor_sync(0xffffffffu, t, off));
            float mnew = fmaxf(mrow[i], t);
            float corr = __expf(mrow[i] - mnew);
            mrow[i] = mnew;
            float rs = 0.f;
#pragma unroll
            for (int j = 0; j < 4; j++) {
                sv[i][j] = __expf(sv[i][j] - mnew);
                rs += sv[i][j];
            }
#pragma unroll
            for (int off = 1; off < 16; off <<= 1)
                rs += __shfl_xor_sync(0xffffffffu, rs, off);
            lrow[i] = lrow[i] * corr + rs;
#pragma unroll
            for (int j = 0; j < 4; j++) o[i][j] *= corr;
        }

        __syncthreads();   // all KPs (K) reads finished
#pragma unroll
        for (int i = 0; i < 8; i++)
            *(float4*)&KPs[(ty * 8 + i) * 64 + tx * 4] = *(float4*)&sv[i][0];
        __syncthreads();   // P visible

        // O += P @ V
#pragma unroll 4
        for (int mm = 0; mm < 64; mm++) {
            float4 v4 = *(const float4*)&Vs[mm * 64 + tx * 4];
#pragma unroll
            for (int i = 0; i < 8; i++) {
                float p = KPs[(ty * 8 + i) * 64 + mm];
                o[i][0] += p * v4.x;
                o[i][1] += p * v4.y;
                o[i][2] += p * v4.z;
                o[i][3] += p * v4.w;
            }
        }
    }

    // finalize and store (B,N,H*64) layout for the projection GEMM
#pragma unroll
    for (int i = 0; i < 8; i++) {
        float invl = 1.f / lrow[i];
        int n = qt * 64 + ty * 8 + i;
        float4 v;
        v.x = o[i][0] * invl;
        v.y = o[i][1] * invl;
        v.z = o[i][2] * invl;
        v.w = o[i][3] * invl;
        *(float4*)&g_ao[(size_t)(b * NN + n) * DIMM + h * HD + tx * 4] = v;
    }
}

// ---------------- launch ----------------
extern "C" void kernel_launch(void* const* d_in, const int* in_sizes, int n_in,
                              void* d_out, int out_size)
{
    const float* x      = (const float*)d_in[0];
    const float* qkv_w  = (const float*)d_in[1];
    const float* qkv_b  = (const float*)d_in[2];
    const float* proj_w = (const float*)d_in[3];
    const float* proj_b = (const float*)d_in[4];
    const float* h1_w   = (const float*)d_in[5];
    const float* h1_b   = (const float*)d_in[6];
    const float* h2_w   = (const float*)d_in[7];
    const float* h2_b   = (const float*)d_in[8];
    const float* freq_w = (const float*)d_in[9];
    float* out = (float*)d_out;

    // QKV = x @ qkv_w + qkv_b   -> g_qkv
    sgemm_bias<<<dim3(QKV_N / 128, M_ROWS / 128), 256>>>(x, qkv_w, qkv_b, nullptr, QKV_N, DIMM);
    // means
    rowmean_kernel<<<M_ROWS / 8, 256>>>(x);
    colmean_kernel<<<dim3(BB, DIMM / 128), 128>>>(x);
    // DCT features + MLP -> f, coef
    prep_kernel<<<BB, 256>>>(h1_w, h1_b, h2_w, h2_b);
    // fused attention -> g_ao
    attn_kernel<<<dim3(NN / 64, BB * HH), 128>>>(freq_w);
    // out = g_ao @ proj_w + proj_b
    sgemm_bias<<<dim3(DIMM / 128, M_ROWS / 128), 256>>>(nullptr, proj_w, proj_b, out, DIMM, DIMM);
}

// round 2
// speedup vs baseline: 2.0839x; 2.0839x over previous
#include <cuda_runtime.h>
#include <math.h>

#define BB 16
#define NN 1024
#define DIMM 512
#define HH 8
#define QKV_N 1536
#define M_ROWS (BB*NN)          // 16384
#define QSCALE 0.125f
#define PI_F 3.14159265358979323846f

// ---------------- scratch ----------------
__device__ float g_qkv[(size_t)M_ROWS * QKV_N];
__device__ float g_ao[(size_t)M_ROWS * DIMM];
__device__ float g_xmean[M_ROWS];
__device__ float g_xavg[BB * DIMM];
__device__ float g_f[BB * NN];
__device__ float g_coef[BB * NN];

// ---------------- tf32 helpers ----------------
__device__ __forceinline__ unsigned f2tf(float x) {
    unsigned r;
    asm("cvt.rna.tf32.f32 %0, %1;" : "=r"(r) : "f"(x));
    return r;
}
__device__ __forceinline__ float uaf(unsigned u) { return __uint_as_float(u); }

__device__ __forceinline__ void mma_tf32(float* d, const unsigned* a, const unsigned* b) {
    asm volatile(
        "mma.sync.aligned.m16n8k8.row.col.f32.tf32.tf32.f32 "
        "{%0,%1,%2,%3},{%4,%5,%6,%7},{%8,%9},{%0,%1,%2,%3};"
        : "+f"(d[0]), "+f"(d[1]), "+f"(d[2]), "+f"(d[3])
        : "r"(a[0]), "r"(a[1]), "r"(a[2]), "r"(a[3]), "r"(b[0]), "r"(b[1]));
}

// ---------------- TF32 tensor-core GEMM: C = A(MxK)@B(KxNc) + bias ----------------
// 128x128 CTA tile, BK=16, 8 warps (2x4), warp tile 64x32.
// Aarg==nullptr -> g_ao ; Carg==nullptr -> g_qkv
#define LDK 136   // = 8 (mod 32) -> conflict-free fragment loads
__global__ __launch_bounds__(256) void gemm_tc(
    const float* Aarg, const float* __restrict__ Bm,
    const float* __restrict__ bias, float* Carg, int Nc, int K)
{
    const float* A = Aarg ? Aarg : g_ao;
    float*       C = Carg ? Carg : g_qkv;

    __shared__ float As[16 * LDK];   // [k][m]
    __shared__ float Bs[16 * LDK];   // [k][n]

    int tid = threadIdx.x, lane = tid & 31, warp = tid >> 5;
    int bx = blockIdx.x, by = blockIdx.y;
    int wm = (warp >> 2) * 64, wn = (warp & 3) * 32;
    int rg = lane >> 2, lc = lane & 3;

    float acc[4][4][4];
#pragma unroll
    for (int i = 0; i < 4; i++)
#pragma unroll
        for (int j = 0; j < 4; j++)
#pragma unroll
            for (int t = 0; t < 4; t++) acc[i][j][t] = 0.f;

    // loaders: A tile 128x16, B tile 16x128, two float4 each
    int mA = tid >> 2, kgA = tid & 3;        // second: mA+64, same kg
    int kB = tid >> 5, nB = (tid & 31) * 4;  // second: kB+8, same n
    const float* pA0 = A + (size_t)(by * 128 + mA) * K + kgA * 4;
    const float* pA1 = pA0 + (size_t)64 * K;
    const float* pB0 = Bm + (size_t)kB * Nc + bx * 128 + nB;
    const float* pB1 = pB0 + (size_t)8 * Nc;

    int nk = K / 16;
    float4 a0v = *(const float4*)pA0;
    float4 a1v = *(const float4*)pA1;
    float4 b0v = *(const float4*)pB0;
    float4 b1v = *(const float4*)pB1;

    for (int kt = 0; kt < nk; kt++) {
        // store (convert to tf32 bits)
        {
            int kb = kgA * 4;
            As[(kb + 0) * LDK + mA] = uaf(f2tf(a0v.x));
            As[(kb + 1) * LDK + mA] = uaf(f2tf(a0v.y));
            As[(kb + 2) * LDK + mA] = uaf(f2tf(a0v.z));
            As[(kb + 3) * LDK + mA] = uaf(f2tf(a0v.w));
            As[(kb + 0) * LDK + mA + 64] = uaf(f2tf(a1v.x));
            As[(kb + 1) * LDK + mA + 64] = uaf(f2tf(a1v.y));
            As[(kb + 2) * LDK + mA + 64] = uaf(f2tf(a1v.z));
            As[(kb + 3) * LDK + mA + 64] = uaf(f2tf(a1v.w));
            float4 c0, c1;
            c0.x = uaf(f2tf(b0v.x)); c0.y = uaf(f2tf(b0v.y));
            c0.z = uaf(f2tf(b0v.z)); c0.w = uaf(f2tf(b0v.w));
            c1.x = uaf(f2tf(b1v.x)); c1.y = uaf(f2tf(b1v.y));
            c1.z = uaf(f2tf(b1v.z)); c1.w = uaf(f2tf(b1v.w));
            *(float4*)&Bs[kB * LDK + nB] = c0;
            *(float4*)&Bs[(kB + 8) * LDK + nB] = c1;
        }
        __syncthreads();
        if (kt + 1 < nk) {
            pA0 += 16; pA1 += 16;
            pB0 += (size_t)16 * Nc; pB1 += (size_t)16 * Nc;
            a0v = *(const float4*)pA0;
            a1v = *(const float4*)pA1;
            b0v = *(const float4*)pB0;
            b1v = *(const float4*)pB1;
        }
#pragma unroll
        for (int ks = 0; ks < 16; ks += 8) {
            unsigned af[4][4], bf[4][2];
#pragma unroll
            for (int mf = 0; mf < 4; mf++) {
                int mb = wm + mf * 16 + rg;
                af[mf][0] = *(const unsigned*)&As[(ks + lc) * LDK + mb];
                af[mf][1] = *(const unsigned*)&As[(ks + lc) * LDK + mb + 8];
                af[mf][2] = *(const unsigned*)&As[(ks + lc + 4) * LDK + mb];
                af[mf][3] = *(const unsigned*)&As[(ks + lc + 4) * LDK + mb + 8];
            }
#pragma unroll
            for (int nf = 0; nf < 4; nf++) {
                int nb = wn + nf * 8 + rg;
                bf[nf][0] = *(const unsigned*)&Bs[(ks + lc) * LDK + nb];
                bf[nf][1] = *(const unsigned*)&Bs[(ks + lc + 4) * LDK + nb];
            }
#pragma unroll
            for (int mf = 0; mf < 4; mf++)
#pragma unroll
                for (int nf = 0; nf < 4; nf++)
                    mma_tf32(acc[mf][nf], af[mf], bf[nf]);
        }
        __syncthreads();
    }

    // epilogue
#pragma unroll
    for (int mf = 0; mf < 4; mf++) {
        int row0 = by * 128 + wm + mf * 16 + rg;
#pragma unroll
        for (int nf = 0; nf < 4; nf++) {
            int col = bx * 128 + wn + nf * 8 + 2 * lc;
            float bz0 = bias[col], bz1 = bias[col + 1];
            float2 v0, v1;
            v0.x = acc[mf][nf][0] + bz0; v0.y = acc[mf][nf][1] + bz1;
            v1.x = acc[mf][nf][2] + bz0; v1.y = acc[mf][nf][3] + bz1;
            *(float2*)&C[(size_t)row0 * Nc + col] = v0;
            *(float2*)&C[(size_t)(row0 + 8) * Nc + col] = v1;
        }
    }
}

// ---------------- per-row mean over DIM ----------------
__global__ void rowmean_kernel(const float* __restrict__ x)
{
    int row = blockIdx.x * 8 + (threadIdx.x >> 5);
    int lane = threadIdx.x & 31;
    const float* p = x + (size_t)row * DIMM;
    float s = 0.f;
#pragma unroll
    for (int c = lane * 4; c < DIMM; c += 128) {
        float4 v = *(const float4*)(p + c);
        s += (v.x + v.y) + (v.z + v.w);
    }
#pragma unroll
    for (int o = 16; o; o >>= 1) s += __shfl_xor_sync(0xffffffffu, s, o);
    if (lane == 0) g_xmean[row] = s * (1.f / DIMM);
}

// ---------------- per-column mean over N ----------------
__global__ void colmean_kernel(const float* __restrict__ x)
{
    int b = blockIdx.x;
    int c = blockIdx.y * 128 + threadIdx.x;
    const float* p = x + (size_t)b * NN * DIMM + c;
    float s0 = 0.f, s1 = 0.f, s2 = 0.f, s3 = 0.f;
    for (int n = 0; n < NN; n += 4) {
        s0 += p[(n + 0) * DIMM];
        s1 += p[(n + 1) * DIMM];
        s2 += p[(n + 2) * DIMM];
        s3 += p[(n + 3) * DIMM];
    }
    g_xavg[b * DIMM + c] = (s0 + s1 + s2 + s3) * (1.f / NN);
}

// ---------------- DCT features + head MLP -> f, coef ----------------
__global__ void prep_kernel(const float* __restrict__ h1_w, const float* __restrict__ h1_b,
                            const float* __restrict__ h2_w, const float* __restrict__ h2_b)
{
    int b = blockIdx.x, tid = threadIdx.x;
    __shared__ float D[32][33], Am[32][33], T[32][33];
    __shared__ float fbuf[1024];
    __shared__ float xa[512], hid[128], red[256];
    __shared__ float s_norm, s_F, s_s2;

    for (int idx = tid; idx < 1024; idx += 256) {
        int k = idx >> 5, n = idx & 31;
        float v;
        if (k == 0) v = sqrtf(1.f / 32.f);
        else v = sqrtf(2.f / 32.f) * cosf(PI_F * (2.f * n + 1.f) * (float)k / 64.f);
        D[k][n] = v;
    }
    for (int idx = tid; idx < 1024; idx += 256)
        Am[idx >> 5][idx & 31] = g_xmean[b * NN + idx];
    xa[tid]       = g_xavg[b * DIMM + tid];
    xa[tid + 256] = g_xavg[b * DIMM + tid + 256];
    __syncthreads();

    for (int idx = tid; idx < 1024; idx += 256) {
        int k = idx >> 5, n = idx & 31;
        float s = 0.f;
#pragma unroll
        for (int m = 0; m < 32; m++) s += D[k][m] * Am[m][n];
        T[k][n] = s;
    }
    __syncthreads();

    float myv[4];
    float sq = 0.f;
#pragma unroll
    for (int u = 0; u < 4; u++) {
        int idx = tid + u * 256;
        int k = idx >> 5, l = idx & 31;
        float s = 0.f;
#pragma unroll
        for (int n = 0; n < 32; n++) s += T[k][n] * D[l][n];
        s = fminf(fmaxf(s, -10.f), 10.f);
        myv[u] = s;
        sq += s * s;
    }
    red[tid] = sq;
    __syncthreads();
    for (int o = 128; o; o >>= 1) { if (tid < o) red[tid] += red[tid + o]; __syncthreads(); }
    if (tid == 0) s_norm = sqrtf(red[0]) + 1e-5f;
    __syncthreads();

    float inv = 1.f / s_norm;
    float sumf = 0.f;
#pragma unroll
    for (int u = 0; u < 4; u++) {
        myv[u] *= inv;
        fbuf[tid + u * 256] = myv[u];
        sumf += myv[u];
    }
    red[tid] = sumf;
    __syncthreads();
    for (int o = 128; o; o >>= 1) { if (tid < o) red[tid] += red[tid + o]; __syncthreads(); }
    if (tid == 0) s_F = red[0];
    __syncthreads();

    if (tid < 128) {
        float s = h1_b[tid];
        for (int c = 0; c < 512; c++) s += xa[c] * h1_w[c * 128 + tid];
        hid[tid] = fmaxf(s, 0.f);
    }
    __syncthreads();
    if (tid < 8) {
        float s = h2_b[tid];
        for (int j = 0; j < 128; j++) s += hid[j] * h2_w[j * 8 + tid];
        red[tid] = s * s;
    }
    __syncthreads();
    if (tid == 0)
        s_s2 = red[0] + red[1] + red[2] + red[3] + red[4] + red[5] + red[6] + red[7];
    __syncthreads();

    float s2 = s_s2, F = s_F;
#pragma unroll
    for (int u = 0; u < 4; u++) {
        int idx = tid + u * 256;
        float fv = fbuf[idx];
        g_f[b * NN + idx] = fv;
        float num = s2 * fv;
        g_coef[b * NN + idx] = num / fmaxf(num * F, 1e-5f);
    }
}

// ---------------- TF32 tensor-core flash attention ----------------
// grid (N/64, B*H), block 128 (4 warps x 16 q-rows). Q in registers (A-frags),
// K/V staged in smem (tf32), P reuses K buffer, O in C-frag registers.
#define LDA 72   // = 8 (mod 32): conflict-free fragment access
__global__ __launch_bounds__(128) void attn_tc(const float* __restrict__ freq_w)
{
    __shared__ float KP[64 * LDA];  // K: [d][m] ; then P: [key][q]
    __shared__ float Vs[64 * LDA];  // V: [m][d]
    __shared__ float fs[64];

    int qt = blockIdx.x, bh = blockIdx.y;
    int b = bh >> 3, h = bh & 7;
    int tid = threadIdx.x, lane = tid & 31, warp = tid >> 5;
    int rg = lane >> 2, lc = lane & 3;
    int q0 = warp * 16;

    float aw = 1.f / (1.f + __expf(-freq_w[0]));
    float one_aw = 1.f - aw;

    // Q fragments for all 8 d-steps (scaled, tf32)
    unsigned qa[8][4];
    {
        const float* qp0 = g_qkv + (size_t)(b * NN + qt * 64 + q0 + rg) * QKV_N + h * 64;
        const float* qp1 = qp0 + (size_t)8 * QKV_N;
#pragma unroll
        for (int ds = 0; ds < 8; ds++) {
            qa[ds][0] = f2tf(__ldg(qp0 + 8 * ds + lc) * QSCALE);
            qa[ds][1] = f2tf(__ldg(qp1 + 8 * ds + lc) * QSCALE);
            qa[ds][2] = f2tf(__ldg(qp0 + 8 * ds + lc + 4) * QSCALE);
            qa[ds][3] = f2tf(__ldg(qp1 + 8 * ds + lc + 4) * QSCALE);
        }
    }
    float coef0 = g_coef[b * NN + qt * 64 + q0 + rg];
    float coef1 = g_coef[b * NN + qt * 64 + q0 + rg + 8];

    float m0 = -1e30f, m1 = -1e30f, l0 = 0.f, l1 = 0.f;
    float o[8][4];
#pragma unroll
    for (int nf = 0; nf < 8; nf++)
#pragma unroll
        for (int t = 0; t < 4; t++) o[nf][t] = 0.f;

    int mloc = tid >> 1, dh = (tid & 1) * 32;
    const float* kbase = g_qkv + (size_t)(b * NN + mloc) * QKV_N + 512 + h * 64 + dh;

    for (int kt = 0; kt < 16; kt++) {
        __syncthreads();   // prior tile's P/V consumers done
        {
            const float* ksrc = kbase + (size_t)kt * 64 * QKV_N;
            const float* vsrc = ksrc + 512;
#pragma unroll
            for (int u = 0; u < 8; u++) {
                float4 kv = *(const float4*)(ksrc + 4 * u);
                int d = dh + 4 * u;
                KP[(d + 0) * LDA + mloc] = uaf(f2tf(kv.x));
                KP[(d + 1) * LDA + mloc] = uaf(f2tf(kv.y));
                KP[(d + 2) * LDA + mloc] = uaf(f2tf(kv.z));
                KP[(d + 3) * LDA + mloc] = uaf(f2tf(kv.w));
                float4 vv = *(const float4*)(vsrc + 4 * u);
                float4 vc;
                vc.x = uaf(f2tf(vv.x)); vc.y = uaf(f2tf(vv.y));
                vc.z = uaf(f2tf(vv.z)); vc.w = uaf(f2tf(vv.w));
                *(float4*)&Vs[mloc * LDA + d] = vc;
            }
            if (tid < 64) fs[tid] = g_f[b * NN + kt * 64 + tid];
        }
        __syncthreads();

        // S = Q K^T via mma
        float sf[8][4];
#pragma unroll
        for (int nf = 0; nf < 8; nf++)
#pragma unroll
            for (int t = 0; t < 4; t++) sf[nf][t] = 0.f;
#pragma unroll
        for (int ds = 0; ds < 8; ds++) {
#pragma unroll
            for (int nf = 0; nf < 8; nf++) {
                unsigned bb[2];
                bb[0] = *(const unsigned*)&KP[(8 * ds + lc) * LDA + 8 * nf + rg];
                bb[1] = *(const unsigned*)&KP[(8 * ds + 4 + lc) * LDA + 8 * nf + rg];
                mma_tf32(sf[nf], qa[ds], bb);
            }
        }

        // rank-1 frequency mix
#pragma unroll
        for (int nf = 0; nf < 8; nf++) {
            float f0v = fs[8 * nf + 2 * lc], f1v = fs[8 * nf + 2 * lc + 1];
            float fa;
            fa = fminf(fmaxf(coef0 * f0v, 0.f), 1.f); sf[nf][0] = one_aw * sf[nf][0] + aw * fa;
            fa = fminf(fmaxf(coef0 * f1v, 0.f), 1.f); sf[nf][1] = one_aw * sf[nf][1] + aw * fa;
            fa = fminf(fmaxf(coef1 * f0v, 0.f), 1.f); sf[nf][2] = one_aw * sf[nf][2] + aw * fa;
            fa = fminf(fmaxf(coef1 * f1v, 0.f), 1.f); sf[nf][3] = one_aw * sf[nf][3] + aw * fa;
        }

        // online softmax (rows r=rg and rg+8 owned by quad lanes)
        float rm0 = -1e30f, rm1 = -1e30f;
#pragma unroll
        for (int nf = 0; nf < 8; nf++) {
            rm0 = fmaxf(rm0, fmaxf(sf[nf][0], sf[nf][1]));
            rm1 = fmaxf(rm1, fmaxf(sf[nf][2], sf[nf][3]));
        }
        rm0 = fmaxf(rm0, __shfl_xor_sync(0xffffffffu, rm0, 1));
        rm0 = fmaxf(rm0, __shfl_xor_sync(0xffffffffu, rm0, 2));
        rm1 = fmaxf(rm1, __shfl_xor_sync(0xffffffffu, rm1, 1));
        rm1 = fmaxf(rm1, __shfl_xor_sync(0xffffffffu, rm1, 2));
        float mn0 = fmaxf(m0, rm0), mn1 = fmaxf(m1, rm1);
        float corr0 = __expf(m0 - mn0), corr1 = __expf(m1 - mn1);
        m0 = mn0; m1 = mn1;
        float rs0 = 0.f, rs1 = 0.f;
#pragma unroll
        for (int nf = 0; nf < 8; nf++) {
            sf[nf][0] = __expf(sf[nf][0] - m0); rs0 += sf[nf][0];
            sf[nf][1] = __expf(sf[nf][1] - m0); rs0 += sf[nf][1];
            sf[nf][2] = __expf(sf[nf][2] - m1); rs1 += sf[nf][2];
            sf[nf][3] = __expf(sf[nf][3] - m1); rs1 += sf[nf][3];
        }
        rs0 += __shfl_xor_sync(0xffffffffu, rs0, 1);
        rs0 += __shfl_xor_sync(0xffffffffu, rs0, 2);
        rs1 += __shfl_xor_sync(0xffffffffu, rs1, 1);
        rs1 += __shfl_xor_sync(0xffffffffu, rs1, 2);
        l0 = l0 * corr0 + rs0;
        l1 = l1 * corr1 + rs1;
#pragma unroll
        for (int nf = 0; nf < 8; nf++) {
            o[nf][0] *= corr0; o[nf][1] *= corr0;
            o[nf][2] *= corr1; o[nf][3] *= corr1;
        }

        __syncthreads();   // all warps done reading K from KP
        // store P (tf32) into KP as [key][q]
#pragma unroll
        for (int nf = 0; nf < 8; nf++) {
            int k2 = 8 * nf + 2 * lc;
            KP[(k2 + 0) * LDA + q0 + rg]     = uaf(f2tf(sf[nf][0]));
            KP[(k2 + 1) * LDA + q0 + rg]     = uaf(f2tf(sf[nf][1]));
            KP[(k2 + 0) * LDA + q0 + rg + 8] = uaf(f2tf(sf[nf][2]));
            KP[(k2 + 1) * LDA + q0 + rg + 8] = uaf(f2tf(sf[nf][3]));
        }
        __syncthreads();   // P visible

        // O += P @ V
#pragma unroll
        for (int ks = 0; ks < 8; ks++) {
            unsigned pa[4];
            pa[0] = *(const unsigned*)&KP[(8 * ks + lc) * LDA + q0 + rg];
            pa[1] = *(const unsigned*)&KP[(8 * ks + lc) * LDA + q0 + rg + 8];
            pa[2] = *(const unsigned*)&KP[(8 * ks + 4 + lc) * LDA + q0 + rg];
            pa[3] = *(const unsigned*)&KP[(8 * ks + 4 + lc) * LDA + q0 + rg + 8];
#pragma unroll
            for (int nf = 0; nf < 8; nf++) {
                unsigned bb[2];
                bb[0] = *(const unsigned*)&Vs[(8 * ks + lc) * LDA + 8 * nf + rg];
                bb[1] = *(const unsigned*)&Vs[(8 * ks + 4 + lc) * LDA + 8 * nf + rg];
                mma_tf32(o[nf], pa, bb);
            }
        }
    }

    // finalize
    float iv0 = 1.f / l0, iv1 = 1.f / l1;
    float* op0 = g_ao + (size_t)(b * NN + qt * 64 + q0 + rg) * DIMM + h * 64;
    float* op1 = op0 + (size_t)8 * DIMM;
#pragma unroll
    for (int nf = 0; nf < 8; nf++) {
        int c = 8 * nf + 2 * lc;
        float2 v0, v1;
        v0.x = o[nf][0] * iv0; v0.y = o[nf][1] * iv0;
        v1.x = o[nf][2] * iv1; v1.y = o[nf][3] * iv1;
        *(float2*)&op0[c] = v0;
        *(float2*)&op1[c] = v1;
    }
}

// ---------------- launch ----------------
extern "C" void kernel_launch(void* const* d_in, const int* in_sizes, int n_in,
                              void* d_out, int out_size)
{
    const float* x      = (const float*)d_in[0];
    const float* qkv_w  = (const float*)d_in[1];
    const float* qkv_b  = (const float*)d_in[2];
    const float* proj_w = (const float*)d_in[3];
    const float* proj_b = (const float*)d_in[4];
    const float* h1_w   = (const float*)d_in[5];
    const float* h1_b   = (const float*)d_in[6];
    const float* h2_w   = (const float*)d_in[7];
    const float* h2_b   = (const float*)d_in[8];
    const float* freq_w = (const float*)d_in[9];
    float* out = (float*)d_out;

    gemm_tc<<<dim3(QKV_N / 128, M_ROWS / 128), 256>>>(x, qkv_w, qkv_b, nullptr, QKV_N, DIMM);
    rowmean_kernel<<<M_ROWS / 8, 256>>>(x);
    colmean_kernel<<<dim3(BB, DIMM / 128), 128>>>(x);
    prep_kernel<<<BB, 256>>>(h1_w, h1_b, h2_w, h2_b);
    attn_tc<<<dim3(NN / 64, BB * HH), 128>>>(freq_w);
    gemm_tc<<<dim3(DIMM / 128, M_ROWS / 128), 256>>>(nullptr, proj_w, proj_b, out, DIMM, DIMM);
}

// round 3
// speedup vs baseline: 3.9468x; 1.8939x over previous
#include <cuda_runtime.h>
#include <cuda_fp16.h>
#include <math.h>

#define BB 16
#define NN 1024
#define DIMM 512
#define HH 8
#define QKV_N 1536
#define M_ROWS (BB*NN)
#define QSCALE 0.125f
#define PI_F 3.14159265358979323846f

// ---------------- scratch ----------------
__device__ __half g_qkvh[(size_t)M_ROWS * QKV_N];  // half QKV (Q pre-scaled)
__device__ float g_ao[(size_t)M_ROWS * DIMM];
__device__ float g_xmean[M_ROWS];
__device__ float g_xavg[BB * DIMM];
__device__ float g_f[BB * NN];
__device__ float g_coef[BB * NN];

// ---------------- helpers ----------------
__device__ __forceinline__ unsigned pack2h(float a, float b) {
    __half2 h = __floats2half2_rn(a, b);
    return *(unsigned*)&h;
}
__device__ __forceinline__ void mma_f16(float* d, const unsigned* a, const unsigned* b) {
    asm volatile(
        "mma.sync.aligned.m16n8k16.row.col.f32.f16.f16.f32 "
        "{%0,%1,%2,%3},{%4,%5,%6,%7},{%8,%9},{%0,%1,%2,%3};"
        : "+f"(d[0]), "+f"(d[1]), "+f"(d[2]), "+f"(d[3])
        : "r"(a[0]), "r"(a[1]), "r"(a[2]), "r"(a[3]), "r"(b[0]), "r"(b[1]));
}
__device__ __forceinline__ void ldsm4(unsigned* r, const void* p) {
    unsigned a = (unsigned)__cvta_generic_to_shared(p);
    asm volatile("ldmatrix.sync.aligned.m8n8.x4.shared.b16 {%0,%1,%2,%3}, [%4];"
                 : "=r"(r[0]), "=r"(r[1]), "=r"(r[2]), "=r"(r[3]) : "r"(a));
}
__device__ __forceinline__ void ldsm4t(unsigned* r, const void* p) {
    unsigned a = (unsigned)__cvta_generic_to_shared(p);
    asm volatile("ldmatrix.sync.aligned.m8n8.x4.trans.shared.b16 {%0,%1,%2,%3}, [%4];"
                 : "=r"(r[0]), "=r"(r[1]), "=r"(r[2]), "=r"(r[3]) : "r"(a));
}
__device__ __forceinline__ void cp16(void* dst, const void* src) {
    unsigned d = (unsigned)__cvta_generic_to_shared(dst);
    asm volatile("cp.async.cg.shared.global [%0], [%1], 16;" :: "r"(d), "l"(src));
}
#define CP_COMMIT() asm volatile("cp.async.commit_group;" ::: "memory")
#define CP_WAIT1()  asm volatile("cp.async.wait_group 1;" ::: "memory")
#define CP_WAIT0()  asm volatile("cp.async.wait_group 0;" ::: "memory")

// ---------------- FP16 tensor-core GEMM ----------------
// C = A(MxK fp32) @ B(KxNc fp32) + bias.  128x128 CTA, BK=32, double-buffered.
// mode 0: fp32 out to Carg.  mode 1: half out to g_qkvh (scale QSCALE for col<512).
#define LDA_G 40    // halves per A row (32 + 8 pad) -> 80B stride
#define LDB_G 136   // halves per B row (128 + 8 pad) -> 272B stride
__global__ __launch_bounds__(256) void hgemm(
    const float* Aarg, const float* __restrict__ Bm,
    const float* __restrict__ bias, float* Carg, int Nc, int K, int mode)
{
    const float* A = Aarg ? Aarg : g_ao;
    __shared__ __half As[2][128 * LDA_G];
    __shared__ __half Bs[2][32 * LDB_G];

    int tid = threadIdx.x, lane = tid & 31, warp = tid >> 5;
    int bx = blockIdx.x, by = blockIdx.y;
    int wm = (warp >> 2) * 64, wn = (warp & 3) * 32;
    int rg = lane >> 2, lc = lane & 3;

    float acc[4][4][4];
#pragma unroll
    for (int i = 0; i < 4; i++)
#pragma unroll
        for (int j = 0; j < 4; j++)
#pragma unroll
            for (int t = 0; t < 4; t++) acc[i][j][t] = 0.f;

    // loaders: A 128x32 (thread: row=tid>>1, 16 floats), B 32x128 (row=tid>>3, 16 floats)
    int ra = tid >> 1, ka = (tid & 1) * 16;
    int rb = tid >> 3, nb = (tid & 7) * 16;
    const float* pA = A + (size_t)(by * 128 + ra) * K + ka;
    const float* pB = Bm + (size_t)rb * Nc + bx * 128 + nb;

    float4 av[4], bv[4];
    int nk = K / 32;

    // preload tile 0 -> regs -> stage 0
#pragma unroll
    for (int u = 0; u < 4; u++) { av[u] = *(const float4*)(pA + 4 * u); bv[u] = *(const float4*)(pB + (size_t)0 + 4 * u); }
#pragma unroll
    for (int u = 0; u < 2; u++) {
        uint4 w;
        w.x = pack2h(av[2*u].x, av[2*u].y);   w.y = pack2h(av[2*u].z, av[2*u].w);
        w.z = pack2h(av[2*u+1].x, av[2*u+1].y); w.w = pack2h(av[2*u+1].z, av[2*u+1].w);
        *(uint4*)&As[0][ra * LDA_G + ka + 8 * u] = w;
        uint4 v;
        v.x = pack2h(bv[2*u].x, bv[2*u].y);   v.y = pack2h(bv[2*u].z, bv[2*u].w);
        v.z = pack2h(bv[2*u+1].x, bv[2*u+1].y); v.w = pack2h(bv[2*u+1].z, bv[2*u+1].w);
        *(uint4*)&Bs[0][rb * LDB_G + nb + 8 * u] = v;
    }
    // preload tile 1 -> regs
    if (nk > 1) {
#pragma unroll
        for (int u = 0; u < 4; u++) {
            av[u] = *(const float4*)(pA + 32 + 4 * u);
            bv[u] = *(const float4*)(pB + (size_t)32 * Nc + 4 * u);
        }
    }

    for (int kt = 0; kt < nk; kt++) {
        __syncthreads();
        int st = kt & 1;
        if (kt + 1 < nk) {
            int sn = st ^ 1;
#pragma unroll
            for (int u = 0; u < 2; u++) {
                uint4 w;
                w.x = pack2h(av[2*u].x, av[2*u].y);   w.y = pack2h(av[2*u].z, av[2*u].w);
                w.z = pack2h(av[2*u+1].x, av[2*u+1].y); w.w = pack2h(av[2*u+1].z, av[2*u+1].w);
                *(uint4*)&As[sn][ra * LDA_G + ka + 8 * u] = w;
                uint4 v;
                v.x = pack2h(bv[2*u].x, bv[2*u].y);   v.y = pack2h(bv[2*u].z, bv[2*u].w);
                v.z = pack2h(bv[2*u+1].x, bv[2*u+1].y); v.w = pack2h(bv[2*u+1].z, bv[2*u+1].w);
                *(uint4*)&Bs[sn][rb * LDB_G + nb + 8 * u] = v;
            }
        }
        if (kt + 2 < nk) {
            const float* qA = pA + (size_t)(kt + 2) * 32;
            const float* qB = pB + (size_t)(kt + 2) * 32 * Nc;
#pragma unroll
            for (int u = 0; u < 4; u++) { av[u] = *(const float4*)(qA + 4 * u); bv[u] = *(const float4*)(qB + 4 * u); }
        }

        int sel = lane >> 3, l7 = lane & 7;
#pragma unroll
        for (int ks = 0; ks < 2; ks++) {
            int k0 = ks * 16;
            unsigned af[4][4], bfr[8];
#pragma unroll
            for (int mf = 0; mf < 4; mf++) {
                int row = wm + 16 * mf + (sel & 1) * 8 + l7;
                int col = k0 + (sel >> 1) * 8;
                ldsm4(af[mf], &As[st][row * LDA_G + col]);
            }
#pragma unroll
            for (int p = 0; p < 2; p++) {
                int row = k0 + (sel & 1) * 8 + l7;
                int col = wn + p * 16 + (sel >> 1) * 8;
                ldsm4t(&bfr[p * 4], &Bs[st][row * LDB_G + col]);
            }
#pragma unroll
            for (int mf = 0; mf < 4; mf++)
#pragma unroll
                for (int nf = 0; nf < 4; nf++)
                    mma_f16(acc[mf][nf], af[mf], &bfr[nf * 2]);
        }
    }

    // epilogue
#pragma unroll
    for (int mf = 0; mf < 4; mf++) {
        int row0 = by * 128 + wm + mf * 16 + rg;
#pragma unroll
        for (int nf = 0; nf < 4; nf++) {
            int col = bx * 128 + wn + nf * 8 + 2 * lc;
            float bz0 = bias[col], bz1 = bias[col + 1];
            if (mode == 0) {
                float2 v0, v1;
                v0.x = acc[mf][nf][0] + bz0; v0.y = acc[mf][nf][1] + bz1;
                v1.x = acc[mf][nf][2] + bz0; v1.y = acc[mf][nf][3] + bz1;
                *(float2*)&Carg[(size_t)row0 * Nc + col] = v0;
                *(float2*)&Carg[(size_t)(row0 + 8) * Nc + col] = v1;
            } else {
                float sc = (col < 512) ? QSCALE : 1.f;
                unsigned h0 = pack2h((acc[mf][nf][0] + bz0) * sc, (acc[mf][nf][1] + bz1) * sc);
                unsigned h1 = pack2h((acc[mf][nf][2] + bz0) * sc, (acc[mf][nf][3] + bz1) * sc);
                *(unsigned*)&g_qkvh[(size_t)row0 * QKV_N + col] = h0;
                *(unsigned*)&g_qkvh[(size_t)(row0 + 8) * QKV_N + col] = h1;
            }
        }
    }
}

// ---------------- per-row mean over DIM ----------------
__global__ void rowmean_kernel(const float* __restrict__ x)
{
    int row = blockIdx.x * 8 + (threadIdx.x >> 5);
    int lane = threadIdx.x & 31;
    const float* p = x + (size_t)row * DIMM;
    float s = 0.f;
#pragma unroll
    for (int c = lane * 4; c < DIMM; c += 128) {
        float4 v = *(const float4*)(p + c);
        s += (v.x + v.y) + (v.z + v.w);
    }
#pragma unroll
    for (int o = 16; o; o >>= 1) s += __shfl_xor_sync(0xffffffffu, s, o);
    if (lane == 0) g_xmean[row] = s * (1.f / DIMM);
}

// ---------------- per-column mean over N ----------------
__global__ void colmean_kernel(const float* __restrict__ x)
{
    int b = blockIdx.x;
    int c = blockIdx.y * 128 + threadIdx.x;
    const float* p = x + (size_t)b * NN * DIMM + c;
    float s0 = 0.f, s1 = 0.f, s2 = 0.f, s3 = 0.f;
    for (int n = 0; n < NN; n += 4) {
        s0 += p[(n + 0) * DIMM];
        s1 += p[(n + 1) * DIMM];
        s2 += p[(n + 2) * DIMM];
        s3 += p[(n + 3) * DIMM];
    }
    g_xavg[b * DIMM + c] = (s0 + s1 + s2 + s3) * (1.f / NN);
}

// ---------------- DCT features + head MLP -> f, coef ----------------
__global__ void prep_kernel(const float* __restrict__ h1_w, const float* __restrict__ h1_b,
                            const float* __restrict__ h2_w, const float* __restrict__ h2_b)
{
    int b = blockIdx.x, tid = threadIdx.x;
    __shared__ float D[32][33], Am[32][33], T[32][33];
    __shared__ float fbuf[1024];
    __shared__ float xa[512], hid[128], red[256];
    __shared__ float s_norm, s_F, s_s2;

    for (int idx = tid; idx < 1024; idx += 256) {
        int k = idx >> 5, n = idx & 31;
        float v;
        if (k == 0) v = sqrtf(1.f / 32.f);
        else v = sqrtf(2.f / 32.f) * cosf(PI_F * (2.f * n + 1.f) * (float)k / 64.f);
        D[k][n] = v;
    }
    for (int idx = tid; idx < 1024; idx += 256)
        Am[idx >> 5][idx & 31] = g_xmean[b * NN + idx];
    xa[tid]       = g_xavg[b * DIMM + tid];
    xa[tid + 256] = g_xavg[b * DIMM + tid + 256];
    __syncthreads();

    for (int idx = tid; idx < 1024; idx += 256) {
        int k = idx >> 5, n = idx & 31;
        float s = 0.f;
#pragma unroll
        for (int m = 0; m < 32; m++) s += D[k][m] * Am[m][n];
        T[k][n] = s;
    }
    __syncthreads();

    float myv[4];
    float sq = 0.f;
#pragma unroll
    for (int u = 0; u < 4; u++) {
        int idx = tid + u * 256;
        int k = idx >> 5, l = idx & 31;
        float s = 0.f;
#pragma unroll
        for (int n = 0; n < 32; n++) s += T[k][n] * D[l][n];
        s = fminf(fmaxf(s, -10.f), 10.f);
        myv[u] = s;
        sq += s * s;
    }
    red[tid] = sq;
    __syncthreads();
    for (int o = 128; o; o >>= 1) { if (tid < o) red[tid] += red[tid + o]; __syncthreads(); }
    if (tid == 0) s_norm = sqrtf(red[0]) + 1e-5f;
    __syncthreads();

    float inv = 1.f / s_norm;
    float sumf = 0.f;
#pragma unroll
    for (int u = 0; u < 4; u++) {
        myv[u] *= inv;
        fbuf[tid + u * 256] = myv[u];
        sumf += myv[u];
    }
    red[tid] = sumf;
    __syncthreads();
    for (int o = 128; o; o >>= 1) { if (tid < o) red[tid] += red[tid + o]; __syncthreads(); }
    if (tid == 0) s_F = red[0];
    __syncthreads();

    if (tid < 128) {
        float a0 = 0.f, a1 = 0.f, a2 = 0.f, a3 = 0.f;
        for (int c = 0; c < 512; c += 4) {
            a0 += xa[c + 0] * h1_w[(c + 0) * 128 + tid];
            a1 += xa[c + 1] * h1_w[(c + 1) * 128 + tid];
            a2 += xa[c + 2] * h1_w[(c + 2) * 128 + tid];
            a3 += xa[c + 3] * h1_w[(c + 3) * 128 + tid];
        }
        hid[tid] = fmaxf((a0 + a1) + (a2 + a3) + h1_b[tid], 0.f);
    }
    __syncthreads();
    if (tid < 8) {
        float s = h2_b[tid];
        for (int j = 0; j < 128; j++) s += hid[j] * h2_w[j * 8 + tid];
        red[tid] = s * s;
    }
    __syncthreads();
    if (tid == 0)
        s_s2 = red[0] + red[1] + red[2] + red[3] + red[4] + red[5] + red[6] + red[7];
    __syncthreads();

    float s2 = s_s2, F = s_F;
#pragma unroll
    for (int u = 0; u < 4; u++) {
        int idx = tid + u * 256;
        float fv = fbuf[idx];
        g_f[b * NN + idx] = fv;
        float num = s2 * fv;
        g_coef[b * NN + idx] = num / fmaxf(num * F, 1e-5f);
    }
}

// ---------------- FP16 tensor-core flash attention ----------------
// grid (N/64, B*H), block 128. Q pre-scaled half in g_qkvh. K/V streamed via
// cp.async (double-buffered). P lives entirely in registers (C-frag == A-frag).
#define LDK_A 72    // halves per K/V row (64 + 8 pad) -> 144B stride
__global__ __launch_bounds__(128) void attn_tc(const float* __restrict__ freq_w)
{
    __shared__ __half Ks[2][64 * LDK_A];
    __shared__ __half Vs[2][64 * LDK_A];
    __shared__ float fsb[2][64];

    int qt = blockIdx.x, bh = blockIdx.y;
    int b = bh >> 3, h = bh & 7;
    int tid = threadIdx.x, lane = tid & 31, warp = tid >> 5;
    int rg = lane >> 2, lc = lane & 3;
    int q0 = warp * 16;

    float aw = 1.f / (1.f + __expf(-freq_w[0]));
    float one_aw = 1.f - aw;

    // Q fragments (half, pre-scaled): 4 d-steps x 4 regs
    unsigned qa[4][4];
    {
        const __half* qp0 = g_qkvh + (size_t)(b * NN + qt * 64 + q0 + rg) * QKV_N + h * 64;
        const __half* qp1 = qp0 + (size_t)8 * QKV_N;
#pragma unroll
        for (int ds = 0; ds < 4; ds++) {
            qa[ds][0] = *(const unsigned*)(qp0 + 16 * ds + 2 * lc);
            qa[ds][1] = *(const unsigned*)(qp1 + 16 * ds + 2 * lc);
            qa[ds][2] = *(const unsigned*)(qp0 + 16 * ds + 2 * lc + 8);
            qa[ds][3] = *(const unsigned*)(qp1 + 16 * ds + 2 * lc + 8);
        }
    }
    float coef0 = g_coef[b * NN + qt * 64 + q0 + rg];
    float coef1 = g_coef[b * NN + qt * 64 + q0 + rg + 8];

    float m0 = -1e30f, m1 = -1e30f, l0 = 0.f, l1 = 0.f;
    float o[8][4];
#pragma unroll
    for (int nf = 0; nf < 8; nf++)
#pragma unroll
        for (int t = 0; t < 4; t++) o[nf][t] = 0.f;

    // tile loader (cp.async): 64 rows, 128B K + 128B V per row
    int lr = tid >> 1, lseg = tid & 1;
    const __half* kb = g_qkvh + (size_t)(b * NN + lr) * QKV_N + 512 + h * 64 + lseg * 32;

    // preload tile 0
    {
        const __half* ks = kb;
#pragma unroll
        for (int u = 0; u < 4; u++) {
            cp16(&Ks[0][lr * LDK_A + lseg * 32 + 8 * u], ks + 8 * u);
            cp16(&Vs[0][lr * LDK_A + lseg * 32 + 8 * u], ks + 512 + 8 * u);
        }
        if (tid < 16) cp16(&fsb[0][tid * 4], g_f + b * NN + tid * 4);
        CP_COMMIT();
    }

    int sel = lane >> 3, l7 = lane & 7;

    for (int kt = 0; kt < 16; kt++) {
        int st = kt & 1;
        if (kt + 1 < 16) {
            const __half* ks = kb + (size_t)(kt + 1) * 64 * QKV_N;
            int sn = st ^ 1;
#pragma unroll
            for (int u = 0; u < 4; u++) {
                cp16(&Ks[sn][lr * LDK_A + lseg * 32 + 8 * u], ks + 8 * u);
                cp16(&Vs[sn][lr * LDK_A + lseg * 32 + 8 * u], ks + 512 + 8 * u);
            }
            if (tid < 16) cp16(&fsb[sn][tid * 4], g_f + b * NN + (kt + 1) * 64 + tid * 4);
            CP_COMMIT();
            CP_WAIT1();
        } else {
            CP_WAIT0();
        }
        __syncthreads();

        // S = Q K^T
        float sf[8][4];
#pragma unroll
        for (int nf = 0; nf < 8; nf++)
#pragma unroll
            for (int t = 0; t < 4; t++) sf[nf][t] = 0.f;
#pragma unroll
        for (int ds = 0; ds < 4; ds++) {
            int d0 = 16 * ds;
#pragma unroll
            for (int p = 0; p < 4; p++) {
                unsigned bfr[4];
                int row = p * 16 + (sel >> 1) * 8 + l7;
                int col = d0 + (sel & 1) * 8;
                ldsm4(bfr, &Ks[st][row * LDK_A + col]);
                mma_f16(sf[2 * p],     qa[ds], &bfr[0]);
                mma_f16(sf[2 * p + 1], qa[ds], &bfr[2]);
            }
        }

        // rank-1 frequency mix
#pragma unroll
        for (int nf = 0; nf < 8; nf++) {
            float f0v = fsb[st][8 * nf + 2 * lc], f1v = fsb[st][8 * nf + 2 * lc + 1];
            float fa;
            fa = fminf(fmaxf(coef0 * f0v, 0.f), 1.f); sf[nf][0] = one_aw * sf[nf][0] + aw * fa;
            fa = fminf(fmaxf(coef0 * f1v, 0.f), 1.f); sf[nf][1] = one_aw * sf[nf][1] + aw * fa;
            fa = fminf(fmaxf(coef1 * f0v, 0.f), 1.f); sf[nf][2] = one_aw * sf[nf][2] + aw * fa;
            fa = fminf(fmaxf(coef1 * f1v, 0.f), 1.f); sf[nf][3] = one_aw * sf[nf][3] + aw * fa;
        }

        // online softmax
        float rm0 = -1e30f, rm1 = -1e30f;
#pragma unroll
        for (int nf = 0; nf < 8; nf++) {
            rm0 = fmaxf(rm0, fmaxf(sf[nf][0], sf[nf][1]));
            rm1 = fmaxf(rm1, fmaxf(sf[nf][2], sf[nf][3]));
        }
        rm0 = fmaxf(rm0, __shfl_xor_sync(0xffffffffu, rm0, 1));
        rm0 = fmaxf(rm0, __shfl_xor_sync(0xffffffffu, rm0, 2));
        rm1 = fmaxf(rm1, __shfl_xor_sync(0xffffffffu, rm1, 1));
        rm1 = fmaxf(rm1, __shfl_xor_sync(0xffffffffu, rm1, 2));
        float mn0 = fmaxf(m0, rm0), mn1 = fmaxf(m1, rm1);
        float corr0 = __expf(m0 - mn0), corr1 = __expf(m1 - mn1);
        m0 = mn0; m1 = mn1;
        float rs0 = 0.f, rs1 = 0.f;
#pragma unroll
        for (int nf = 0; nf < 8; nf++) {
            sf[nf][0] = __expf(sf[nf][0] - m0); rs0 += sf[nf][0];
            sf[nf][1] = __expf(sf[nf][1] - m0); rs0 += sf[nf][1];
            sf[nf][2] = __expf(sf[nf][2] - m1); rs1 += sf[nf][2];
            sf[nf][3] = __expf(sf[nf][3] - m1); rs1 += sf[nf][3];
        }
        rs0 += __shfl_xor_sync(0xffffffffu, rs0, 1);
        rs0 += __shfl_xor_sync(0xffffffffu, rs0, 2);
        rs1 += __shfl_xor_sync(0xffffffffu, rs1, 1);
        rs1 += __shfl_xor_sync(0xffffffffu, rs1, 2);
        l0 = l0 * corr0 + rs0;
        l1 = l1 * corr1 + rs1;
#pragma unroll
        for (int nf = 0; nf < 8; nf++) {
            o[nf][0] *= corr0; o[nf][1] *= corr0;
            o[nf][2] *= corr1; o[nf][3] *= corr1;
        }

        // O += P @ V   (P: C-frag == A-frag, pure registers)
#pragma unroll
        for (int j = 0; j < 4; j++) {
            unsigned pa[4];
            pa[0] = pack2h(sf[2*j][0],   sf[2*j][1]);
            pa[1] = pack2h(sf[2*j][2],   sf[2*j][3]);
            pa[2] = pack2h(sf[2*j+1][0], sf[2*j+1][1]);
            pa[3] = pack2h(sf[2*j+1][2], sf[2*j+1][3]);
            int k0 = 16 * j;
#pragma unroll
            for (int p = 0; p < 4; p++) {
                unsigned bfr[4];
                int row = k0 + (sel & 1) * 8 + l7;
                int col = p * 16 + (sel >> 1) * 8;
                ldsm4t(bfr, &Vs[st][row * LDK_A + col]);
                mma_f16(o[2 * p],     pa, &bfr[0]);
                mma_f16(o[2 * p + 1], pa, &bfr[2]);
            }
        }
        __syncthreads();   // reads of stage st done before it is refilled
    }

    // finalize
    float iv0 = 1.f / l0, iv1 = 1.f / l1;
    float* op0 = g_ao + (size_t)(b * NN + qt * 64 + q0 + rg) * DIMM + h * 64;
    float* op1 = op0 + (size_t)8 * DIMM;
#pragma unroll
    for (int nf = 0; nf < 8; nf++) {
        int c = 8 * nf + 2 * lc;
        float2 v0, v1;
        v0.x = o[nf][0] * iv0; v0.y = o[nf][1] * iv0;
        v1.x = o[nf][2] * iv1; v1.y = o[nf][3] * iv1;
        *(float2*)&op0[c] = v0;
        *(float2*)&op1[c] = v1;
    }
}

// ---------------- launch ----------------
extern "C" void kernel_launch(void* const* d_in, const int* in_sizes, int n_in,
                              void* d_out, int out_size)
{
    const float* x      = (const float*)d_in[0];
    const float* qkv_w  = (const float*)d_in[1];
    const float* qkv_b  = (const float*)d_in[2];
    const float* proj_w = (const float*)d_in[3];
    const float* proj_b = (const float*)d_in[4];
    const float* h1_w   = (const float*)d_in[5];
    const float* h1_b   = (const float*)d_in[6];
    const float* h2_w   = (const float*)d_in[7];
    const float* h2_b   = (const float*)d_in[8];
    const float* freq_w = (const float*)d_in[9];
    float* out = (float*)d_out;

    hgemm<<<dim3(QKV_N / 128, M_ROWS / 128), 256>>>(x, qkv_w, qkv_b, nullptr, QKV_N, DIMM, 1);
    rowmean_kernel<<<M_ROWS / 8, 256>>>(x);
    colmean_kernel<<<dim3(BB, DIMM / 128), 128>>>(x);
    prep_kernel<<<BB, 256>>>(h1_w, h1_b, h2_w, h2_b);
    attn_tc<<<dim3(NN / 64, BB * HH), 128>>>(freq_w);
    hgemm<<<dim3(DIMM / 128, M_ROWS / 128), 256>>>(nullptr, proj_w, proj_b, out, DIMM, DIMM, 0);
}

// round 4
// speedup vs baseline: 4.6283x; 1.1727x over previous
#include <cuda_runtime.h>
#include <cuda_fp16.h>
#include <math.h>

#define BB 16
#define NN 1024
#define DIMM 512
#define HH 8
#define QKV_N 1536
#define M_ROWS (BB*NN)
#define QSCALE 0.125f
#define PI_F 3.14159265358979323846f

// ---------------- scratch ----------------
__device__ __half g_qkvh[(size_t)M_ROWS * QKV_N];  // half QKV (Q pre-scaled)
__device__ __half g_aoh[(size_t)M_ROWS * DIMM];    // half attention out
__device__ __half g_xh[(size_t)M_ROWS * DIMM];     // half x
__device__ __half g_wqkv[DIMM * QKV_N];            // half qkv_w
__device__ __half g_wproj[DIMM * DIMM];            // half proj_w
__device__ float g_xmean[M_ROWS];
__device__ float g_xavg[BB * DIMM];
__device__ float g_f[BB * NN];
__device__ float g_coef[BB * NN];

// ---------------- helpers ----------------
__device__ __forceinline__ unsigned pack2h(float a, float b) {
    __half2 h = __floats2half2_rn(a, b);
    return *(unsigned*)&h;
}
__device__ __forceinline__ void mma_f16(float* d, const unsigned* a, const unsigned* b) {
    asm volatile(
        "mma.sync.aligned.m16n8k16.row.col.f32.f16.f16.f32 "
        "{%0,%1,%2,%3},{%4,%5,%6,%7},{%8,%9},{%0,%1,%2,%3};"
        : "+f"(d[0]), "+f"(d[1]), "+f"(d[2]), "+f"(d[3])
        : "r"(a[0]), "r"(a[1]), "r"(a[2]), "r"(a[3]), "r"(b[0]), "r"(b[1]));
}
__device__ __forceinline__ void ldsm4(unsigned* r, const void* p) {
    unsigned a = (unsigned)__cvta_generic_to_shared(p);
    asm volatile("ldmatrix.sync.aligned.m8n8.x4.shared.b16 {%0,%1,%2,%3}, [%4];"
                 : "=r"(r[0]), "=r"(r[1]), "=r"(r[2]), "=r"(r[3]) : "r"(a));
}
__device__ __forceinline__ void ldsm4t(unsigned* r, const void* p) {
    unsigned a = (unsigned)__cvta_generic_to_shared(p);
    asm volatile("ldmatrix.sync.aligned.m8n8.x4.trans.shared.b16 {%0,%1,%2,%3}, [%4];"
                 : "=r"(r[0]), "=r"(r[1]), "=r"(r[2]), "=r"(r[3]) : "r"(a));
}
__device__ __forceinline__ void cp16(void* dst, const void* src) {
    unsigned d = (unsigned)__cvta_generic_to_shared(dst);
    asm volatile("cp.async.cg.shared.global [%0], [%1], 16;" :: "r"(d), "l"(src));
}
#define CP_COMMIT() asm volatile("cp.async.commit_group;" ::: "memory")
#define CP_WAIT1()  asm volatile("cp.async.wait_group 1;" ::: "memory")
#define CP_WAIT0()  asm volatile("cp.async.wait_group 0;" ::: "memory")

// ---------------- converts ----------------
// x -> half, fused row-mean. 8 rows/block, warp per row.
__global__ void convx_kernel(const float* __restrict__ x)
{
    int row = blockIdx.x * 8 + (threadIdx.x >> 5);
    int lane = threadIdx.x & 31;
    const float* p = x + (size_t)row * DIMM;
    __half* q = g_xh + (size_t)row * DIMM;
    float s = 0.f;
#pragma unroll
    for (int i = 0; i < 4; i++) {
        int c = lane * 4 + i * 128;
        float4 v = *(const float4*)(p + c);
        s += (v.x + v.y) + (v.z + v.w);
        uint2 w;
        w.x = pack2h(v.x, v.y);
        w.y = pack2h(v.z, v.w);
        *(uint2*)(q + c) = w;
    }
#pragma unroll
    for (int o = 16; o; o >>= 1) s += __shfl_xor_sync(0xffffffffu, s, o);
    if (lane == 0) g_xmean[row] = s * (1.f / DIMM);
}

// weights -> half (qkv_w then proj_w), float4-granular
__global__ void convw_kernel(const float* __restrict__ qw, const float* __restrict__ pw)
{
    int i = blockIdx.x * 256 + threadIdx.x;   // 262144 float4 total
    float4 v;
    uint2 w;
    if (i < 196608) {
        v = ((const float4*)qw)[i];
        w.x = pack2h(v.x, v.y); w.y = pack2h(v.z, v.w);
        *(uint2*)&g_wqkv[4 * i] = w;
    } else {
        v = ((const float4*)pw)[i - 196608];
        w.x = pack2h(v.x, v.y); w.y = pack2h(v.z, v.w);
        *(uint2*)&g_wproj[4 * (i - 196608)] = w;
    }
}

// ---------------- per-column mean over N ----------------
__global__ void colmean_kernel(const float* __restrict__ x)
{
    int b = blockIdx.x;
    int c = blockIdx.y * 128 + threadIdx.x;
    const float* p = x + (size_t)b * NN * DIMM + c;
    float s0 = 0.f, s1 = 0.f, s2 = 0.f, s3 = 0.f;
    for (int n = 0; n < NN; n += 4) {
        s0 += p[(n + 0) * DIMM];
        s1 += p[(n + 1) * DIMM];
        s2 += p[(n + 2) * DIMM];
        s3 += p[(n + 3) * DIMM];
    }
    g_xavg[b * DIMM + c] = (s0 + s1 + s2 + s3) * (1.f / NN);
}

// ---------------- pure-half tensor-core GEMM ----------------
// mode 1: A=g_xh, B=g_wqkv, out half -> g_qkvh (QSCALE on cols<512), Nc=1536
// mode 0: A=g_aoh, B=g_wproj, out fp32+bias -> Cf, Nc=512
#define LDA_G 40    // halves per A smem row (32+8)
#define LDB_G 136   // halves per B smem row (128+8)
__global__ __launch_bounds__(256) void hgemm(
    const float* __restrict__ bias, float* Cf, int Nc, int K, int mode)
{
    const __half* A = mode ? g_xh : g_aoh;
    const __half* Bm = mode ? g_wqkv : g_wproj;

    __shared__ __half As[2][128 * LDA_G];
    __shared__ __half Bs[2][32 * LDB_G];

    int tid = threadIdx.x, lane = tid & 31, warp = tid >> 5;
    int bx = blockIdx.x, by = blockIdx.y;
    int wm = (warp >> 2) * 64, wn = (warp & 3) * 32;
    int rg = lane >> 2, lc = lane & 3;

    float acc[4][4][4];
#pragma unroll
    for (int i = 0; i < 4; i++)
#pragma unroll
        for (int j = 0; j < 4; j++)
#pragma unroll
            for (int t = 0; t < 4; t++) acc[i][j][t] = 0.f;

    // A: 128x32 half tile = 512 x 16B chunks; B: 32x128 = 512 chunks. 2 each.
    int ca0 = tid * 2, ca1 = tid * 2 + 1;
    int ra0 = ca0 >> 2, sa0 = (ca0 & 3) * 8;
    int ra1 = ca1 >> 2, sa1 = (ca1 & 3) * 8;
    int rb0 = ca0 >> 4, sb0 = (ca0 & 15) * 8;
    int rb1 = ca1 >> 4, sb1 = (ca1 & 15) * 8;
    const __half* pA = A + (size_t)(by * 128) * K;
    const __half* pB = Bm + (size_t)bx * 128;

    int nk = K / 32;
    // preload tile 0 -> stage 0
    cp16(&As[0][ra0 * LDA_G + sa0], pA + (size_t)ra0 * K + sa0);
    cp16(&As[0][ra1 * LDA_G + sa1], pA + (size_t)ra1 * K + sa1);
    cp16(&Bs[0][rb0 * LDB_G + sb0], pB + (size_t)rb0 * Nc + sb0);
    cp16(&Bs[0][rb1 * LDB_G + sb1], pB + (size_t)rb1 * Nc + sb1);
    CP_COMMIT();

    int sel = lane >> 3, l7 = lane & 7;

    for (int kt = 0; kt < nk; kt++) {
        int st = kt & 1;
        if (kt + 1 < nk) {
            int sn = st ^ 1, k0 = (kt + 1) * 32;
            cp16(&As[sn][ra0 * LDA_G + sa0], pA + (size_t)ra0 * K + k0 + sa0);
            cp16(&As[sn][ra1 * LDA_G + sa1], pA + (size_t)ra1 * K + k0 + sa1);
            cp16(&Bs[sn][rb0 * LDB_G + sb0], pB + (size_t)(k0 + rb0) * Nc + sb0);
            cp16(&Bs[sn][rb1 * LDB_G + sb1], pB + (size_t)(k0 + rb1) * Nc + sb1);
            CP_COMMIT();
            CP_WAIT1();
        } else {
            CP_WAIT0();
        }
        __syncthreads();

#pragma unroll
        for (int ks = 0; ks < 2; ks++) {
            int k0 = ks * 16;
            unsigned af[4][4], bfr[8];
#pragma unroll
            for (int mf = 0; mf < 4; mf++) {
                int row = wm + 16 * mf + (sel & 1) * 8 + l7;
                int col = k0 + (sel >> 1) * 8;
                ldsm4(af[mf], &As[st][row * LDA_G + col]);
            }
#pragma unroll
            for (int p = 0; p < 2; p++) {
                int row = k0 + (sel & 1) * 8 + l7;
                int col = wn + p * 16 + (sel >> 1) * 8;
                ldsm4t(&bfr[p * 4], &Bs[st][row * LDB_G + col]);
            }
#pragma unroll
            for (int mf = 0; mf < 4; mf++)
#pragma unroll
                for (int nf = 0; nf < 4; nf++)
                    mma_f16(acc[mf][nf], af[mf], &bfr[nf * 2]);
        }
        __syncthreads();
    }

    // epilogue
#pragma unroll
    for (int mf = 0; mf < 4; mf++) {
        int row0 = by * 128 + wm + mf * 16 + rg;
#pragma unroll
        for (int nf = 0; nf < 4; nf++) {
            int col = bx * 128 + wn + nf * 8 + 2 * lc;
            float bz0 = bias[col], bz1 = bias[col + 1];
            if (mode == 0) {
                float2 v0, v1;
                v0.x = acc[mf][nf][0] + bz0; v0.y = acc[mf][nf][1] + bz1;
                v1.x = acc[mf][nf][2] + bz0; v1.y = acc[mf][nf][3] + bz1;
                *(float2*)&Cf[(size_t)row0 * Nc + col] = v0;
                *(float2*)&Cf[(size_t)(row0 + 8) * Nc + col] = v1;
            } else {
                float sc = (col < 512) ? QSCALE : 1.f;
                unsigned h0 = pack2h((acc[mf][nf][0] + bz0) * sc, (acc[mf][nf][1] + bz1) * sc);
                unsigned h1 = pack2h((acc[mf][nf][2] + bz0) * sc, (acc[mf][nf][3] + bz1) * sc);
                *(unsigned*)&g_qkvh[(size_t)row0 * QKV_N + col] = h0;
                *(unsigned*)&g_qkvh[(size_t)(row0 + 8) * QKV_N + col] = h1;
            }
        }
    }
}

// ---------------- DCT features + head MLP -> f, coef ----------------
__global__ void prep_kernel(const float* __restrict__ h1_w, const float* __restrict__ h1_b,
                            const float* __restrict__ h2_w, const float* __restrict__ h2_b)
{
    int b = blockIdx.x, tid = threadIdx.x;
    __shared__ float D[32][33], Am[32][33], T[32][33];
    __shared__ float fbuf[1024];
    __shared__ float xa[512], hid[128], red[256];
    __shared__ float s_norm, s_F, s_s2;

    for (int idx = tid; idx < 1024; idx += 256) {
        int k = idx >> 5, n = idx & 31;
        float v;
        if (k == 0) v = sqrtf(1.f / 32.f);
        else v = sqrtf(2.f / 32.f) * cosf(PI_F * (2.f * n + 1.f) * (float)k / 64.f);
        D[k][n] = v;
    }
    for (int idx = tid; idx < 1024; idx += 256)
        Am[idx >> 5][idx & 31] = g_xmean[b * NN + idx];
    xa[tid]       = g_xavg[b * DIMM + tid];
    xa[tid + 256] = g_xavg[b * DIMM + tid + 256];
    __syncthreads();

    for (int idx = tid; idx < 1024; idx += 256) {
        int k = idx >> 5, n = idx & 31;
        float s = 0.f;
#pragma unroll
        for (int m = 0; m < 32; m++) s += D[k][m] * Am[m][n];
        T[k][n] = s;
    }
    __syncthreads();

    float myv[4];
    float sq = 0.f;
#pragma unroll
    for (int u = 0; u < 4; u++) {
        int idx = tid + u * 256;
        int k = idx >> 5, l = idx & 31;
        float s = 0.f;
#pragma unroll
        for (int n = 0; n < 32; n++) s += T[k][n] * D[l][n];
        s = fminf(fmaxf(s, -10.f), 10.f);
        myv[u] = s;
        sq += s * s;
    }
    red[tid] = sq;
    __syncthreads();
    for (int o = 128; o; o >>= 1) { if (tid < o) red[tid] += red[tid + o]; __syncthreads(); }
    if (tid == 0) s_norm = sqrtf(red[0]) + 1e-5f;
    __syncthreads();

    float inv = 1.f / s_norm;
    float sumf = 0.f;
#pragma unroll
    for (int u = 0; u < 4; u++) {
        myv[u] *= inv;
        fbuf[tid + u * 256] = myv[u];
        sumf += myv[u];
    }
    red[tid] = sumf;
    __syncthreads();
    for (int o = 128; o; o >>= 1) { if (tid < o) red[tid] += red[tid + o]; __syncthreads(); }
    if (tid == 0) s_F = red[0];
    __syncthreads();

    // MLP stage 1: all 256 threads, 2 partials per hidden unit
    {
        int unit = tid & 127, halfsel = tid >> 7;
        int c0 = halfsel * 256;
        float a0 = 0.f, a1 = 0.f, a2 = 0.f, a3 = 0.f;
#pragma unroll 4
        for (int c = c0; c < c0 + 256; c += 4) {
            a0 += xa[c + 0] * h1_w[(c + 0) * 128 + unit];
            a1 += xa[c + 1] * h1_w[(c + 1) * 128 + unit];
            a2 += xa[c + 2] * h1_w[(c + 2) * 128 + unit];
            a3 += xa[c + 3] * h1_w[(c + 3) * 128 + unit];
        }
        red[tid] = (a0 + a1) + (a2 + a3);
    }
    __syncthreads();
    if (tid < 128) hid[tid] = fmaxf(red[tid] + red[tid + 128] + h1_b[tid], 0.f);
    __syncthreads();
    // MLP stage 2: warp w -> output w (8 warps), shuffle reduce
    {
        int w = tid >> 5, lane = tid & 31;
        float s = 0.f;
#pragma unroll
        for (int j = 0; j < 4; j++)
            s += hid[lane + 32 * j] * h2_w[(lane + 32 * j) * 8 + w];
#pragma unroll
        for (int o = 16; o; o >>= 1) s += __shfl_xor_sync(0xffffffffu, s, o);
        if (lane == 0) {
            float t = s + h2_b[w];
            red[w] = t * t;
        }
    }
    __syncthreads();
    if (tid == 0)
        s_s2 = red[0] + red[1] + red[2] + red[3] + red[4] + red[5] + red[6] + red[7];
    __syncthreads();

    float s2 = s_s2, F = s_F;
#pragma unroll
    for (int u = 0; u < 4; u++) {
        int idx = tid + u * 256;
        float fv = fbuf[idx];
        g_f[b * NN + idx] = fv;
        float num = s2 * fv;
        g_coef[b * NN + idx] = num / fmaxf(num * F, 1e-5f);
    }
}

// ---------------- FP16 tensor-core flash attention ----------------
#define LDK_A 72
__global__ __launch_bounds__(128) void attn_tc(const float* __restrict__ freq_w)
{
    __shared__ __half Ks[2][64 * LDK_A];
    __shared__ __half Vs[2][64 * LDK_A];
    __shared__ float fsb[2][64];

    int qt = blockIdx.x, bh = blockIdx.y;
    int b = bh >> 3, h = bh & 7;
    int tid = threadIdx.x, lane = tid & 31, warp = tid >> 5;
    int rg = lane >> 2, lc = lane & 3;
    int q0 = warp * 16;

    float aw = 1.f / (1.f + __expf(-freq_w[0]));
    float one_aw = 1.f - aw;

    unsigned qa[4][4];
    {
        const __half* qp0 = g_qkvh + (size_t)(b * NN + qt * 64 + q0 + rg) * QKV_N + h * 64;
        const __half* qp1 = qp0 + (size_t)8 * QKV_N;
#pragma unroll
        for (int ds = 0; ds < 4; ds++) {
            qa[ds][0] = *(const unsigned*)(qp0 + 16 * ds + 2 * lc);
            qa[ds][1] = *(const unsigned*)(qp1 + 16 * ds + 2 * lc);
            qa[ds][2] = *(const unsigned*)(qp0 + 16 * ds + 2 * lc + 8);
            qa[ds][3] = *(const unsigned*)(qp1 + 16 * ds + 2 * lc + 8);
        }
    }
    float coef0 = g_coef[b * NN + qt * 64 + q0 + rg];
    float coef1 = g_coef[b * NN + qt * 64 + q0 + rg + 8];

    float m0 = -1e30f, m1 = -1e30f, l0 = 0.f, l1 = 0.f;
    float o[8][4];
#pragma unroll
    for (int nf = 0; nf < 8; nf++)
#pragma unroll
        for (int t = 0; t < 4; t++) o[nf][t] = 0.f;

    int lr = tid >> 1, lseg = tid & 1;
    const __half* kb = g_qkvh + (size_t)(b * NN + lr) * QKV_N + 512 + h * 64 + lseg * 32;

    {
#pragma unroll
        for (int u = 0; u < 4; u++) {
            cp16(&Ks[0][lr * LDK_A + lseg * 32 + 8 * u], kb + 8 * u);
            cp16(&Vs[0][lr * LDK_A + lseg * 32 + 8 * u], kb + 512 + 8 * u);
        }
        if (tid < 16) cp16(&fsb[0][tid * 4], g_f + b * NN + tid * 4);
        CP_COMMIT();
    }

    int sel = lane >> 3, l7 = lane & 7;

    for (int kt = 0; kt < 16; kt++) {
        int st = kt & 1;
        if (kt + 1 < 16) {
            const __half* ks = kb + (size_t)(kt + 1) * 64 * QKV_N;
            int sn = st ^ 1;
#pragma unroll
            for (int u = 0; u < 4; u++) {
                cp16(&Ks[sn][lr * LDK_A + lseg * 32 + 8 * u], ks + 8 * u);
                cp16(&Vs[sn][lr * LDK_A + lseg * 32 + 8 * u], ks + 512 + 8 * u);
            }
            if (tid < 16) cp16(&fsb[sn][tid * 4], g_f + b * NN + (kt + 1) * 64 + tid * 4);
            CP_COMMIT();
            CP_WAIT1();
        } else {
            CP_WAIT0();
        }
        __syncthreads();

        float sf[8][4];
#pragma unroll
        for (int nf = 0; nf < 8; nf++)
#pragma unroll
            for (int t = 0; t < 4; t++) sf[nf][t] = 0.f;
#pragma unroll
        for (int ds = 0; ds < 4; ds++) {
            int d0 = 16 * ds;
#pragma unroll
            for (int p = 0; p < 4; p++) {
                unsigned bfr[4];
                int row = p * 16 + (sel >> 1) * 8 + l7;
                int col = d0 + (sel & 1) * 8;
                ldsm4(bfr, &Ks[st][row * LDK_A + col]);
                mma_f16(sf[2 * p],     qa[ds], &bfr[0]);
                mma_f16(sf[2 * p + 1], qa[ds], &bfr[2]);
            }
        }

#pragma unroll
        for (int nf = 0; nf < 8; nf++) {
            float f0v = fsb[st][8 * nf + 2 * lc], f1v = fsb[st][8 * nf + 2 * lc + 1];
            float fa;
            fa = fminf(fmaxf(coef0 * f0v, 0.f), 1.f); sf[nf][0] = one_aw * sf[nf][0] + aw * fa;
            fa = fminf(fmaxf(coef0 * f1v, 0.f), 1.f); sf[nf][1] = one_aw * sf[nf][1] + aw * fa;
            fa = fminf(fmaxf(coef1 * f0v, 0.f), 1.f); sf[nf][2] = one_aw * sf[nf][2] + aw * fa;
            fa = fminf(fmaxf(coef1 * f1v, 0.f), 1.f); sf[nf][3] = one_aw * sf[nf][3] + aw * fa;
        }

        float rm0 = -1e30f, rm1 = -1e30f;
#pragma unroll
        for (int nf = 0; nf < 8; nf++) {
            rm0 = fmaxf(rm0, fmaxf(sf[nf][0], sf[nf][1]));
            rm1 = fmaxf(rm1, fmaxf(sf[nf][2], sf[nf][3]));
        }
        rm0 = fmaxf(rm0, __shfl_xor_sync(0xffffffffu, rm0, 1));
        rm0 = fmaxf(rm0, __shfl_xor_sync(0xffffffffu, rm0, 2));
        rm1 = fmaxf(rm1, __shfl_xor_sync(0xffffffffu, rm1, 1));
        rm1 = fmaxf(rm1, __shfl_xor_sync(0xffffffffu, rm1, 2));
        float mn0 = fmaxf(m0, rm0), mn1 = fmaxf(m1, rm1);
        float corr0 = __expf(m0 - mn0), corr1 = __expf(m1 - mn1);
        m0 = mn0; m1 = mn1;
        float rs0 = 0.f, rs1 = 0.f;
#pragma unroll
        for (int nf = 0; nf < 8; nf++) {
            sf[nf][0] = __expf(sf[nf][0] - m0); rs0 += sf[nf][0];
            sf[nf][1] = __expf(sf[nf][1] - m0); rs0 += sf[nf][1];
            sf[nf][2] = __expf(sf[nf][2] - m1); rs1 += sf[nf][2];
            sf[nf][3] = __expf(sf[nf][3] - m1); rs1 += sf[nf][3];
        }
        rs0 += __shfl_xor_sync(0xffffffffu, rs0, 1);
        rs0 += __shfl_xor_sync(0xffffffffu, rs0, 2);
        rs1 += __shfl_xor_sync(0xffffffffu, rs1, 1);
        rs1 += __shfl_xor_sync(0xffffffffu, rs1, 2);
        l0 = l0 * corr0 + rs0;
        l1 = l1 * corr1 + rs1;
#pragma unroll
        for (int nf = 0; nf < 8; nf++) {
            o[nf][0] *= corr0; o[nf][1] *= corr0;
            o[nf][2] *= corr1; o[nf][3] *= corr1;
        }

#pragma unroll
        for (int j = 0; j < 4; j++) {
            unsigned pa[4];
            pa[0] = pack2h(sf[2*j][0],   sf[2*j][1]);
            pa[1] = pack2h(sf[2*j][2],   sf[2*j][3]);
            pa[2] = pack2h(sf[2*j+1][0], sf[2*j+1][1]);
            pa[3] = pack2h(sf[2*j+1][2], sf[2*j+1][3]);
            int k0 = 16 * j;
#pragma unroll
            for (int p = 0; p < 4; p++) {
                unsigned bfr[4];
                int row = k0 + (sel & 1) * 8 + l7;
                int col = p * 16 + (sel >> 1) * 8;
                ldsm4t(bfr, &Vs[st][row * LDK_A + col]);
                mma_f16(o[2 * p],     pa, &bfr[0]);
                mma_f16(o[2 * p + 1], pa, &bfr[2]);
            }
        }
        __syncthreads();
    }

    // finalize -> half
    float iv0 = 1.f / l0, iv1 = 1.f / l1;
    __half* op0 = g_aoh + (size_t)(b * NN + qt * 64 + q0 + rg) * DIMM + h * 64;
    __half* op1 = op0 + (size_t)8 * DIMM;
#pragma unroll
    for (int nf = 0; nf < 8; nf++) {
        int c = 8 * nf + 2 * lc;
        *(unsigned*)&op0[c] = pack2h(o[nf][0] * iv0, o[nf][1] * iv0);
        *(unsigned*)&op1[c] = pack2h(o[nf][2] * iv1, o[nf][3] * iv1);
    }
}

// ---------------- launch ----------------
extern "C" void kernel_launch(void* const* d_in, const int* in_sizes, int n_in,
                              void* d_out, int out_size)
{
    const float* x      = (const float*)d_in[0];
    const float* qkv_w  = (const float*)d_in[1];
    const float* qkv_b  = (const float*)d_in[2];
    const float* proj_w = (const float*)d_in[3];
    const float* proj_b = (const float*)d_in[4];
    const float* h1_w   = (const float*)d_in[5];
    const float* h1_b   = (const float*)d_in[6];
    const float* h2_w   = (const float*)d_in[7];
    const float* h2_b   = (const float*)d_in[8];
    const float* freq_w = (const float*)d_in[9];
    float* out = (float*)d_out;

    convx_kernel<<<M_ROWS / 8, 256>>>(x);
    convw_kernel<<<1024, 256>>>(qkv_w, proj_w);
    colmean_kernel<<<dim3(BB, DIMM / 128), 128>>>(x);
    hgemm<<<dim3(QKV_N / 128, M_ROWS / 128), 256>>>(qkv_b, nullptr, QKV_N, DIMM, 1);
    prep_kernel<<<BB, 256>>>(h1_w, h1_b, h2_w, h2_b);
    attn_tc<<<dim3(NN / 64, BB * HH), 128>>>(freq_w);
    hgemm<<<dim3(DIMM / 128, M_ROWS / 128), 256>>>(proj_b, out, DIMM, DIMM, 0);
}

// round 5
// speedup vs baseline: 4.6550x; 1.0058x over previous
#include <cuda_runtime.h>
#include <cuda_fp16.h>
#include <math.h>

#define BB 16
#define NN 1024
#define DIMM 512
#define HH 8
#define QKV_N 1536
#define M_ROWS (BB*NN)
#define QSCALE 0.125f
#define PI_F 3.14159265358979323846f

// ---------------- scratch ----------------
__device__ __half g_qkvh[(size_t)M_ROWS * QKV_N];
__device__ __half g_aoh[(size_t)M_ROWS * DIMM];
__device__ __half g_xh[(size_t)M_ROWS * DIMM];
__device__ __half g_wqkv[DIMM * QKV_N];
__device__ __half g_wproj[DIMM * DIMM];
__device__ float g_xmean[M_ROWS];
__device__ float g_xavg[BB * DIMM];
__device__ float g_f[BB * NN];
__device__ float g_coef[BB * NN];

// ---------------- helpers ----------------
__device__ __forceinline__ unsigned pack2h(float a, float b) {
    __half2 h = __floats2half2_rn(a, b);
    return *(unsigned*)&h;
}
__device__ __forceinline__ void mma_f16(float* d, const unsigned* a, const unsigned* b) {
    asm volatile(
        "mma.sync.aligned.m16n8k16.row.col.f32.f16.f16.f32 "
        "{%0,%1,%2,%3},{%4,%5,%6,%7},{%8,%9},{%0,%1,%2,%3};"
        : "+f"(d[0]), "+f"(d[1]), "+f"(d[2]), "+f"(d[3])
        : "r"(a[0]), "r"(a[1]), "r"(a[2]), "r"(a[3]), "r"(b[0]), "r"(b[1]));
}
__device__ __forceinline__ void ldsm4(unsigned* r, const void* p) {
    unsigned a = (unsigned)__cvta_generic_to_shared(p);
    asm volatile("ldmatrix.sync.aligned.m8n8.x4.shared.b16 {%0,%1,%2,%3}, [%4];"
                 : "=r"(r[0]), "=r"(r[1]), "=r"(r[2]), "=r"(r[3]) : "r"(a));
}
__device__ __forceinline__ void ldsm4t(unsigned* r, const void* p) {
    unsigned a = (unsigned)__cvta_generic_to_shared(p);
    asm volatile("ldmatrix.sync.aligned.m8n8.x4.trans.shared.b16 {%0,%1,%2,%3}, [%4];"
                 : "=r"(r[0]), "=r"(r[1]), "=r"(r[2]), "=r"(r[3]) : "r"(a));
}
__device__ __forceinline__ void cp16(void* dst, const void* src) {
    unsigned d = (unsigned)__cvta_generic_to_shared(dst);
    asm volatile("cp.async.cg.shared.global [%0], [%1], 16;" :: "r"(d), "l"(src));
}
#define CP_COMMIT() asm volatile("cp.async.commit_group;" ::: "memory")
#define CP_WAIT2()  asm volatile("cp.async.wait_group 2;" ::: "memory")
#define CP_WAIT1()  asm volatile("cp.async.wait_group 1;" ::: "memory")
#define CP_WAIT0()  asm volatile("cp.async.wait_group 0;" ::: "memory")

// ---------------- converts ----------------
__global__ void convx_kernel(const float* __restrict__ x)
{
    int row = blockIdx.x * 8 + (threadIdx.x >> 5);
    int lane = threadIdx.x & 31;
    const float* p = x + (size_t)row * DIMM;
    __half* q = g_xh + (size_t)row * DIMM;
    float s = 0.f;
#pragma unroll
    for (int i = 0; i < 4; i++) {
        int c = lane * 4 + i * 128;
        float4 v = *(const float4*)(p + c);
        s += (v.x + v.y) + (v.z + v.w);
        uint2 w;
        w.x = pack2h(v.x, v.y);
        w.y = pack2h(v.z, v.w);
        *(uint2*)(q + c) = w;
    }
#pragma unroll
    for (int o = 16; o; o >>= 1) s += __shfl_xor_sync(0xffffffffu, s, o);
    if (lane == 0) g_xmean[row] = s * (1.f / DIMM);
}

__global__ void convw_kernel(const float* __restrict__ qw, const float* __restrict__ pw)
{
    int i = blockIdx.x * 256 + threadIdx.x;
    float4 v;
    uint2 w;
    if (i < 196608) {
        v = ((const float4*)qw)[i];
        w.x = pack2h(v.x, v.y); w.y = pack2h(v.z, v.w);
        *(uint2*)&g_wqkv[4 * i] = w;
    } else {
        v = ((const float4*)pw)[i - 196608];
        w.x = pack2h(v.x, v.y); w.y = pack2h(v.z, v.w);
        *(uint2*)&g_wproj[4 * (i - 196608)] = w;
    }
}

__global__ void colmean_kernel(const float* __restrict__ x)
{
    int b = blockIdx.x;
    int c = blockIdx.y * 128 + threadIdx.x;
    const float* p = x + (size_t)b * NN * DIMM + c;
    float s0 = 0.f, s1 = 0.f, s2 = 0.f, s3 = 0.f;
    for (int n = 0; n < NN; n += 4) {
        s0 += p[(n + 0) * DIMM];
        s1 += p[(n + 1) * DIMM];
        s2 += p[(n + 2) * DIMM];
        s3 += p[(n + 3) * DIMM];
    }
    g_xavg[b * DIMM + c] = (s0 + s1 + s2 + s3) * (1.f / NN);
}

// ---------------- pure-half tensor-core GEMM, v2 ----------------
// Block 128 (4 warps), CTA tile 128x128, warp tile 64x64.
// 4-stage cp.async pipeline, Kc=16 per stage, one __syncthreads per iter.
// mode 1: A=g_xh,B=g_wqkv -> g_qkvh (half, QSCALE on cols<512); mode 0: A=g_aoh,B=g_wproj -> Cf fp32.
#define LDA_G 24    // halves per A smem row (16+8) -> 48B stride (ldsm conflict-free)
#define LDB_G 136   // halves per B smem row (128+8) -> 272B stride (ldsm4t conflict-free)
__global__ __launch_bounds__(128) void hgemm(
    const float* __restrict__ bias, float* Cf, int Nc, int K, int mode)
{
    const __half* A = mode ? g_xh : g_aoh;
    const __half* Bm = mode ? g_wqkv : g_wproj;

    __shared__ __half As[4][128 * LDA_G];   // [m][k]
    __shared__ __half Bs[4][16 * LDB_G];    // [k][n]

    int tid = threadIdx.x, lane = tid & 31, warp = tid >> 5;
    int bx = blockIdx.x, by = blockIdx.y;
    int wm = (warp >> 1) * 64, wn = (warp & 1) * 64;
    int rg = lane >> 2, lc = lane & 3;
    int sel = lane >> 3, l7 = lane & 7;

    float acc[4][8][4];
#pragma unroll
    for (int i = 0; i < 4; i++)
#pragma unroll
        for (int j = 0; j < 8; j++)
#pragma unroll
            for (int t = 0; t < 4; t++) acc[i][j][t] = 0.f;

    // loaders: A stage 128x16 halves (thread t -> row t, 2 chunks);
    //          B stage 16x128 halves (thread t -> row t>>3, n0=(t&7)*16, 2 chunks)
    int brow = tid >> 3, bn0 = (tid & 7) * 16;
    const __half* pA = A + (size_t)(by * 128 + tid) * K;
    const __half* pB = Bm + (size_t)brow * Nc + bx * 128 + bn0;

    int nk = K / 16;
    // preload stages 0..2
#pragma unroll
    for (int s = 0; s < 3; s++) {
        int k0 = s * 16;
        cp16(&As[s][tid * LDA_G], pA + k0);
        cp16(&As[s][tid * LDA_G + 8], pA + k0 + 8);
        cp16(&Bs[s][brow * LDB_G + bn0], pB + (size_t)k0 * Nc);
        cp16(&Bs[s][brow * LDB_G + bn0 + 8], pB + (size_t)k0 * Nc + 8);
        CP_COMMIT();
    }

    for (int kt = 0; kt < nk; kt++) {
        CP_WAIT2();
        __syncthreads();
        if (kt + 3 < nk) {
            int s = (kt + 3) & 3, k0 = (kt + 3) * 16;
            cp16(&As[s][tid * LDA_G], pA + k0);
            cp16(&As[s][tid * LDA_G + 8], pA + k0 + 8);
            cp16(&Bs[s][brow * LDB_G + bn0], pB + (size_t)k0 * Nc);
            cp16(&Bs[s][brow * LDB_G + bn0 + 8], pB + (size_t)k0 * Nc + 8);
        }
        CP_COMMIT();

        int st = kt & 3;
        unsigned af[4][4], bfr[4][4];
#pragma unroll
        for (int mf = 0; mf < 4; mf++) {
            int row = wm + 16 * mf + (sel & 1) * 8 + l7;
            int col = (sel >> 1) * 8;
            ldsm4(af[mf], &As[st][row * LDA_G + col]);
        }
#pragma unroll
        for (int p = 0; p < 4; p++) {
            int row = (sel & 1) * 8 + l7;
            int col = wn + p * 16 + (sel >> 1) * 8;
            ldsm4t(bfr[p], &Bs[st][row * LDB_G + col]);
        }
#pragma unroll
        for (int mf = 0; mf < 4; mf++)
#pragma unroll
            for (int nf = 0; nf < 8; nf++)
                mma_f16(acc[mf][nf], af[mf], &bfr[nf >> 1][(nf & 1) * 2]);
    }

    // epilogue
#pragma unroll
    for (int mf = 0; mf < 4; mf++) {
        int row0 = by * 128 + wm + mf * 16 + rg;
#pragma unroll
        for (int nf = 0; nf < 8; nf++) {
            int col = bx * 128 + wn + nf * 8 + 2 * lc;
            float bz0 = bias[col], bz1 = bias[col + 1];
            if (mode == 0) {
                float2 v0, v1;
                v0.x = acc[mf][nf][0] + bz0; v0.y = acc[mf][nf][1] + bz1;
                v1.x = acc[mf][nf][2] + bz0; v1.y = acc[mf][nf][3] + bz1;
                *(float2*)&Cf[(size_t)row0 * Nc + col] = v0;
                *(float2*)&Cf[(size_t)(row0 + 8) * Nc + col] = v1;
            } else {
                float sc = (col < 512) ? QSCALE : 1.f;
                unsigned h0 = pack2h((acc[mf][nf][0] + bz0) * sc, (acc[mf][nf][1] + bz1) * sc);
                unsigned h1 = pack2h((acc[mf][nf][2] + bz0) * sc, (acc[mf][nf][3] + bz1) * sc);
                *(unsigned*)&g_qkvh[(size_t)row0 * QKV_N + col] = h0;
                *(unsigned*)&g_qkvh[(size_t)(row0 + 8) * QKV_N + col] = h1;
            }
        }
    }
}

// ---------------- DCT features + head MLP -> f, coef ----------------
__global__ void prep_kernel(const float* __restrict__ h1_w, const float* __restrict__ h1_b,
                            const float* __restrict__ h2_w, const float* __restrict__ h2_b)
{
    int b = blockIdx.x, tid = threadIdx.x;
    __shared__ float D[32][33], Am[32][33], T[32][33];
    __shared__ float fbuf[1024];
    __shared__ float xa[512], hid[128], red[256];
    __shared__ float s_norm, s_F, s_s2;

    for (int idx = tid; idx < 1024; idx += 256) {
        int k = idx >> 5, n = idx & 31;
        float v;
        if (k == 0) v = sqrtf(1.f / 32.f);
        else v = sqrtf(2.f / 32.f) * cosf(PI_F * (2.f * n + 1.f) * (float)k / 64.f);
        D[k][n] = v;
    }
    for (int idx = tid; idx < 1024; idx += 256)
        Am[idx >> 5][idx & 31] = g_xmean[b * NN + idx];
    xa[tid]       = g_xavg[b * DIMM + tid];
    xa[tid + 256] = g_xavg[b * DIMM + tid + 256];
    __syncthreads();

    for (int idx = tid; idx < 1024; idx += 256) {
        int k = idx >> 5, n = idx & 31;
        float s = 0.f;
#pragma unroll
        for (int m = 0; m < 32; m++) s += D[k][m] * Am[m][n];
        T[k][n] = s;
    }
    __syncthreads();

    float myv[4];
    float sq = 0.f;
#pragma unroll
    for (int u = 0; u < 4; u++) {
        int idx = tid + u * 256;
        int k = idx >> 5, l = idx & 31;
        float s = 0.f;
#pragma unroll
        for (int n = 0; n < 32; n++) s += T[k][n] * D[l][n];
        s = fminf(fmaxf(s, -10.f), 10.f);
        myv[u] = s;
        sq += s * s;
    }
    red[tid] = sq;
    __syncthreads();
    for (int o = 128; o; o >>= 1) { if (tid < o) red[tid] += red[tid + o]; __syncthreads(); }
    if (tid == 0) s_norm = sqrtf(red[0]) + 1e-5f;
    __syncthreads();

    float inv = 1.f / s_norm;
    float sumf = 0.f;
#pragma unroll
    for (int u = 0; u < 4; u++) {
        myv[u] *= inv;
        fbuf[tid + u * 256] = myv[u];
        sumf += myv[u];
    }
    red[tid] = sumf;
    __syncthreads();
    for (int o = 128; o; o >>= 1) { if (tid < o) red[tid] += red[tid + o]; __syncthreads(); }
    if (tid == 0) s_F = red[0];
    __syncthreads();

    {
        int unit = tid & 127, halfsel = tid >> 7;
        int c0 = halfsel * 256;
        float a0 = 0.f, a1 = 0.f, a2 = 0.f, a3 = 0.f;
#pragma unroll 4
        for (int c = c0; c < c0 + 256; c += 4) {
            a0 += xa[c + 0] * h1_w[(c + 0) * 128 + unit];
            a1 += xa[c + 1] * h1_w[(c + 1) * 128 + unit];
            a2 += xa[c + 2] * h1_w[(c + 2) * 128 + unit];
            a3 += xa[c + 3] * h1_w[(c + 3) * 128 + unit];
        }
        red[tid] = (a0 + a1) + (a2 + a3);
    }
    __syncthreads();
    if (tid < 128) hid[tid] = fmaxf(red[tid] + red[tid + 128] + h1_b[tid], 0.f);
    __syncthreads();
    {
        int w = tid >> 5, lane = tid & 31;
        float s = 0.f;
#pragma unroll
        for (int j = 0; j < 4; j++)
            s += hid[lane + 32 * j] * h2_w[(lane + 32 * j) * 8 + w];
#pragma unroll
        for (int o = 16; o; o >>= 1) s += __shfl_xor_sync(0xffffffffu, s, o);
        if (lane == 0) {
            float t = s + h2_b[w];
            red[w] = t * t;
        }
    }
    __syncthreads();
    if (tid == 0)
        s_s2 = red[0] + red[1] + red[2] + red[3] + red[4] + red[5] + red[6] + red[7];
    __syncthreads();

    float s2 = s_s2, F = s_F;
#pragma unroll
    for (int u = 0; u < 4; u++) {
        int idx = tid + u * 256;
        float fv = fbuf[idx];
        g_f[b * NN + idx] = fv;
        float num = s2 * fv;
        g_coef[b * NN + idx] = num / fmaxf(num * F, 1e-5f);
    }
}

// ---------------- FP16 tensor-core flash attention ----------------
#define LDK_A 72
__global__ __launch_bounds__(128) void attn_tc(const float* __restrict__ freq_w)
{
    __shared__ __half Ks[2][64 * LDK_A];
    __shared__ __half Vs[2][64 * LDK_A];
    __shared__ float fsb[2][64];

    int qt = blockIdx.x, bh = blockIdx.y;
    int b = bh >> 3, h = bh & 7;
    int tid = threadIdx.x, lane = tid & 31, warp = tid >> 5;
    int rg = lane >> 2, lc = lane & 3;
    int q0 = warp * 16;

    float aw = 1.f / (1.f + __expf(-freq_w[0]));
    float one_aw = 1.f - aw;

    unsigned qa[4][4];
    {
        const __half* qp0 = g_qkvh + (size_t)(b * NN + qt * 64 + q0 + rg) * QKV_N + h * 64;
        const __half* qp1 = qp0 + (size_t)8 * QKV_N;
#pragma unroll
        for (int ds = 0; ds < 4; ds++) {
            qa[ds][0] = *(const unsigned*)(qp0 + 16 * ds + 2 * lc);
            qa[ds][1] = *(const unsigned*)(qp1 + 16 * ds + 2 * lc);
            qa[ds][2] = *(const unsigned*)(qp0 + 16 * ds + 2 * lc + 8);
            qa[ds][3] = *(const unsigned*)(qp1 + 16 * ds + 2 * lc + 8);
        }
    }
    float coef0 = g_coef[b * NN + qt * 64 + q0 + rg];
    float coef1 = g_coef[b * NN + qt * 64 + q0 + rg + 8];

    float m0 = -1e30f, m1 = -1e30f, l0 = 0.f, l1 = 0.f;
    float o[8][4];
#pragma unroll
    for (int nf = 0; nf < 8; nf++)
#pragma unroll
        for (int t = 0; t < 4; t++) o[nf][t] = 0.f;

    int lr = tid >> 1, lseg = tid & 1;
    const __half* kb = g_qkvh + (size_t)(b * NN + lr) * QKV_N + 512 + h * 64 + lseg * 32;

    {
#pragma unroll
        for (int u = 0; u < 4; u++) {
            cp16(&Ks[0][lr * LDK_A + lseg * 32 + 8 * u], kb + 8 * u);
            cp16(&Vs[0][lr * LDK_A + lseg * 32 + 8 * u], kb + 512 + 8 * u);
        }
        if (tid < 16) cp16(&fsb[0][tid * 4], g_f + b * NN + tid * 4);
        CP_COMMIT();
    }

    int sel = lane >> 3, l7 = lane & 7;

    for (int kt = 0; kt < 16; kt++) {
        int st = kt & 1;
        if (kt + 1 < 16) {
            const __half* ks = kb + (size_t)(kt + 1) * 64 * QKV_N;
            int sn = st ^ 1;
#pragma unroll
            for (int u = 0; u < 4; u++) {
                cp16(&Ks[sn][lr * LDK_A + lseg * 32 + 8 * u], ks + 8 * u);
                cp16(&Vs[sn][lr * LDK_A + lseg * 32 + 8 * u], ks + 512 + 8 * u);
            }
            if (tid < 16) cp16(&fsb[sn][tid * 4], g_f + b * NN + (kt + 1) * 64 + tid * 4);
            CP_COMMIT();
            CP_WAIT1();
        } else {
            CP_WAIT0();
        }
        __syncthreads();

        float sf[8][4];
#pragma unroll
        for (int nf = 0; nf < 8; nf++)
#pragma unroll
            for (int t = 0; t < 4; t++) sf[nf][t] = 0.f;
#pragma unroll
        for (int ds = 0; ds < 4; ds++) {
            int d0 = 16 * ds;
#pragma unroll
            for (int p = 0; p < 4; p++) {
                unsigned bfr[4];
                int row = p * 16 + (sel >> 1) * 8 + l7;
                int col = d0 + (sel & 1) * 8;
                ldsm4(bfr, &Ks[st][row * LDK_A + col]);
                mma_f16(sf[2 * p],     qa[ds], &bfr[0]);
                mma_f16(sf[2 * p + 1], qa[ds], &bfr[2]);
            }
        }

#pragma unroll
        for (int nf = 0; nf < 8; nf++) {
            float f0v = fsb[st][8 * nf + 2 * lc], f1v = fsb[st][8 * nf + 2 * lc + 1];
            float fa;
            fa = fminf(fmaxf(coef0 * f0v, 0.f), 1.f); sf[nf][0] = one_aw * sf[nf][0] + aw * fa;
            fa = fminf(fmaxf(coef0 * f1v, 0.f), 1.f); sf[nf][1] = one_aw * sf[nf][1] + aw * fa;
            fa = fminf(fmaxf(coef1 * f0v, 0.f), 1.f); sf[nf][2] = one_aw * sf[nf][2] + aw * fa;
            fa = fminf(fmaxf(coef1 * f1v, 0.f), 1.f); sf[nf][3] = one_aw * sf[nf][3] + aw * fa;
        }

        float rm0 = -1e30f, rm1 = -1e30f;
#pragma unroll
        for (int nf = 0; nf < 8; nf++) {
            rm0 = fmaxf(rm0, fmaxf(sf[nf][0], sf[nf][1]));
            rm1 = fmaxf(rm1, fmaxf(sf[nf][2], sf[nf][3]));
        }
        rm0 = fmaxf(rm0, __shfl_xor_sync(0xffffffffu, rm0, 1));
        rm0 = fmaxf(rm0, __shfl_xor_sync(0xffffffffu, rm0, 2));
        rm1 = fmaxf(rm1, __shfl_xor_sync(0xffffffffu, rm1, 1));
        rm1 = fmaxf(rm1, __shfl_xor_sync(0xffffffffu, rm1, 2));
        float mn0 = fmaxf(m0, rm0), mn1 = fmaxf(m1, rm1);
        float corr0 = __expf(m0 - mn0), corr1 = __expf(m1 - mn1);
        m0 = mn0; m1 = mn1;
        float rs0 = 0.f, rs1 = 0.f;
#pragma unroll
        for (int nf = 0; nf < 8; nf++) {
            sf[nf][0] = __expf(sf[nf][0] - m0); rs0 += sf[nf][0];
            sf[nf][1] = __expf(sf[nf][1] - m0); rs0 += sf[nf][1];
            sf[nf][2] = __expf(sf[nf][2] - m1); rs1 += sf[nf][2];
            sf[nf][3] = __expf(sf[nf][3] - m1); rs1 += sf[nf][3];
        }
        rs0 += __shfl_xor_sync(0xffffffffu, rs0, 1);
        rs0 += __shfl_xor_sync(0xffffffffu, rs0, 2);
        rs1 += __shfl_xor_sync(0xffffffffu, rs1, 1);
        rs1 += __shfl_xor_sync(0xffffffffu, rs1, 2);
        l0 = l0 * corr0 + rs0;
        l1 = l1 * corr1 + rs1;
#pragma unroll
        for (int nf = 0; nf < 8; nf++) {
            o[nf][0] *= corr0; o[nf][1] *= corr0;
            o[nf][2] *= corr1; o[nf][3] *= corr1;
        }

#pragma unroll
        for (int j = 0; j < 4; j++) {
            unsigned pa[4];
            pa[0] = pack2h(sf[2*j][0],   sf[2*j][1]);
            pa[1] = pack2h(sf[2*j][2],   sf[2*j][3]);
            pa[2] = pack2h(sf[2*j+1][0], sf[2*j+1][1]);
            pa[3] = pack2h(sf[2*j+1][2], sf[2*j+1][3]);
            int k0 = 16 * j;
#pragma unroll
            for (int p = 0; p < 4; p++) {
                unsigned bfr[4];
                int row = k0 + (sel & 1) * 8 + l7;
                int col = p * 16 + (sel >> 1) * 8;
                ldsm4t(bfr, &Vs[st][row * LDK_A + col]);
                mma_f16(o[2 * p],     pa, &bfr[0]);
                mma_f16(o[2 * p + 1], pa, &bfr[2]);
            }
        }
        __syncthreads();
    }

    float iv0 = 1.f / l0, iv1 = 1.f / l1;
    __half* op0 = g_aoh + (size_t)(b * NN + qt * 64 + q0 + rg) * DIMM + h * 64;
    __half* op1 = op0 + (size_t)8 * DIMM;
#pragma unroll
    for (int nf = 0; nf < 8; nf++) {
        int c = 8 * nf + 2 * lc;
        *(unsigned*)&op0[c] = pack2h(o[nf][0] * iv0, o[nf][1] * iv0);
        *(unsigned*)&op1[c] = pack2h(o[nf][2] * iv1, o[nf][3] * iv1);
    }
}

// ---------------- launch ----------------
extern "C" void kernel_launch(void* const* d_in, const int* in_sizes, int n_in,
                              void* d_out, int out_size)
{
    const float* x      = (const float*)d_in[0];
    const float* qkv_w  = (const float*)d_in[1];
    const float* qkv_b  = (const float*)d_in[2];
    const float* proj_w = (const float*)d_in[3];
    const float* proj_b = (const float*)d_in[4];
    const float* h1_w   = (const float*)d_in[5];
    const float* h1_b   = (const float*)d_in[6];
    const float* h2_w   = (const float*)d_in[7];
    const float* h2_b   = (const float*)d_in[8];
    const float* freq_w = (const float*)d_in[9];
    float* out = (float*)d_out;

    convx_kernel<<<M_ROWS / 8, 256>>>(x);
    convw_kernel<<<1024, 256>>>(qkv_w, proj_w);
    colmean_kernel<<<dim3(BB, DIMM / 128), 128>>>(x);
    hgemm<<<dim3(QKV_N / 128, M_ROWS / 128), 128>>>(qkv_b, nullptr, QKV_N, DIMM, 1);
    prep_kernel<<<BB, 256>>>(h1_w, h1_b, h2_w, h2_b);
    attn_tc<<<dim3(NN / 64, BB * HH), 128>>>(freq_w);
    hgemm<<<dim3(DIMM / 128, M_ROWS / 128), 128>>>(proj_b, out, DIMM, DIMM, 0);
}

// round 9
// speedup vs baseline: 5.6412x; 1.2119x over previous
#include <cuda_runtime.h>
#include <cuda_fp16.h>
#include <math.h>

#define BB 16
#define NN 1024
#define DIMM 512
#define HH 8
#define QKV_N 1536
#define M_ROWS (BB*NN)
#define QSCALE 0.125f
#define PI_F 3.14159265358979323846f

// ---------------- scratch ----------------
__device__ __half g_qkvh[(size_t)M_ROWS * QKV_N];
__device__ __half g_aoh[(size_t)M_ROWS * DIMM];
__device__ __half g_xh[(size_t)M_ROWS * DIMM];
__device__ __half g_wqkv[DIMM * QKV_N];   // [K=512][N=1536]
__device__ __half g_wproj[DIMM * DIMM];   // [K=512][N=512]
__device__ float g_xmean[M_ROWS];
__device__ float g_xavg[BB * DIMM];
__device__ float g_f[BB * NN];
__device__ float g_coef[BB * NN];

// ---------------- helpers ----------------
__device__ __forceinline__ unsigned pack2h(float a, float b) {
    __half2 h = __floats2half2_rn(a, b);
    return *(unsigned*)&h;
}
__device__ __forceinline__ void mma_f16(float* d, const unsigned* a, const unsigned* b) {
    asm volatile(
        "mma.sync.aligned.m16n8k16.row.col.f32.f16.f16.f32 "
        "{%0,%1,%2,%3},{%4,%5,%6,%7},{%8,%9},{%0,%1,%2,%3};"
        : "+f"(d[0]), "+f"(d[1]), "+f"(d[2]), "+f"(d[3])
        : "r"(a[0]), "r"(a[1]), "r"(a[2]), "r"(a[3]), "r"(b[0]), "r"(b[1]));
}
__device__ __forceinline__ void ldsm4(unsigned* r, const void* p) {
    unsigned a = (unsigned)__cvta_generic_to_shared(p);
    asm volatile("ldmatrix.sync.aligned.m8n8.x4.shared.b16 {%0,%1,%2,%3}, [%4];"
                 : "=r"(r[0]), "=r"(r[1]), "=r"(r[2]), "=r"(r[3]) : "r"(a));
}
__device__ __forceinline__ void ldsm4t(unsigned* r, const void* p) {
    unsigned a = (unsigned)__cvta_generic_to_shared(p);
    asm volatile("ldmatrix.sync.aligned.m8n8.x4.trans.shared.b16 {%0,%1,%2,%3}, [%4];"
                 : "=r"(r[0]), "=r"(r[1]), "=r"(r[2]), "=r"(r[3]) : "r"(a));
}
__device__ __forceinline__ void cp16(void* dst, const void* src) {
    unsigned d = (unsigned)__cvta_generic_to_shared(dst);
    asm volatile("cp.async.cg.shared.global [%0], [%1], 16;" :: "r"(d), "l"(src));
}
#define CP_COMMIT() asm volatile("cp.async.commit_group;" ::: "memory")
#define CP_WAIT2()  asm volatile("cp.async.wait_group 2;" ::: "memory")
#define CP_WAIT1()  asm volatile("cp.async.wait_group 1;" ::: "memory")
#define CP_WAIT0()  asm volatile("cp.async.wait_group 0;" ::: "memory")

// ---------------- converts ----------------
__global__ void convx_kernel(const float* __restrict__ x)
{
    int row = blockIdx.x * 8 + (threadIdx.x >> 5);
    int lane = threadIdx.x & 31;
    const float* p = x + (size_t)row * DIMM;
    __half* q = g_xh + (size_t)row * DIMM;
    float s = 0.f;
#pragma unroll
    for (int i = 0; i < 4; i++) {
        int c = lane * 4 + i * 128;
        float4 v = *(const float4*)(p + c);
        s += (v.x + v.y) + (v.z + v.w);
        uint2 w;
        w.x = pack2h(v.x, v.y);
        w.y = pack2h(v.z, v.w);
        *(uint2*)(q + c) = w;
    }
#pragma unroll
    for (int o = 16; o; o >>= 1) s += __shfl_xor_sync(0xffffffffu, s, o);
    if (lane == 0) g_xmean[row] = s * (1.f / DIMM);
}

__global__ void convw_kernel(const float* __restrict__ qw, const float* __restrict__ pw)
{
    int i = blockIdx.x * 256 + threadIdx.x;
    float4 v;
    uint2 w;
    if (i < 196608) {
        v = ((const float4*)qw)[i];
        w.x = pack2h(v.x, v.y); w.y = pack2h(v.z, v.w);
        *(uint2*)&g_wqkv[4 * i] = w;
    } else {
        v = ((const float4*)pw)[i - 196608];
        w.x = pack2h(v.x, v.y); w.y = pack2h(v.z, v.w);
        *(uint2*)&g_wproj[4 * (i - 196608)] = w;
    }
}

__global__ void colmean_kernel(const float* __restrict__ x)
{
    int b = blockIdx.x;
    int c = blockIdx.y * 128 + threadIdx.x;
    const float* p = x + (size_t)b * NN * DIMM + c;
    float s0 = 0.f, s1 = 0.f, s2 = 0.f, s3 = 0.f;
    for (int n = 0; n < NN; n += 4) {
        s0 += p[(n + 0) * DIMM];
        s1 += p[(n + 1) * DIMM];
        s2 += p[(n + 2) * DIMM];
        s3 += p[(n + 3) * DIMM];
    }
    g_xavg[b * DIMM + c] = (s0 + s1 + s2 + s3) * (1.f / NN);
}

// ---------------- hgemm v3: 8 warps, warp tile 64x32, 4-stage, Kc=16 ----------------
#define LDA_G 24    // halves per A smem row (16 + 8 pad)
#define LDB_G 136   // halves per B smem row (128 + 8 pad)
__global__ __launch_bounds__(256) void hgemm(
    const float* __restrict__ bias, float* Cf, int Nc, int K, int mode)
{
    const __half* A = mode ? g_xh : g_aoh;
    const __half* Bm = mode ? g_wqkv : g_wproj;

    __shared__ __half As[4][128 * LDA_G];   // [m][k], 24.0 KB
    __shared__ __half Bs[4][16 * LDB_G];    // [k][n], 17.0 KB

    int tid = threadIdx.x, lane = tid & 31, warp = tid >> 5;
    int bx = blockIdx.x, by = blockIdx.y;
    int wm = (warp >> 2) * 64, wn = (warp & 3) * 32;
    int rg = lane >> 2, lc = lane & 3;
    int sel = lane >> 3, l7 = lane & 7;

    float acc[4][4][4];
#pragma unroll
    for (int i = 0; i < 4; i++)
#pragma unroll
        for (int j = 0; j < 4; j++)
#pragma unroll
            for (int t = 0; t < 4; t++) acc[i][j][t] = 0.f;

    // loaders: A 128x16 (thread: row tid>>1, chunk tid&1); B 16x128 (tid<128: row tid>>3, n0 (tid&7)*16)
    int ar = tid >> 1, ac = (tid & 1) * 8;
    int brow = tid >> 3, bn0 = (tid & 7) * 16;
    const __half* pA = A + (size_t)(by * 128 + ar) * K + ac;
    const __half* pB = Bm + (size_t)brow * Nc + bx * 128 + bn0;
    bool loadB = (tid < 128);

    int nk = K / 16;
    // preload stages 0..2
#pragma unroll
    for (int s = 0; s < 3; s++) {
        int k0 = s * 16;
        cp16(&As[s][ar * LDA_G + ac], pA + k0);
        if (loadB) {
            cp16(&Bs[s][brow * LDB_G + bn0], pB + (size_t)k0 * Nc);
            cp16(&Bs[s][brow * LDB_G + bn0 + 8], pB + (size_t)k0 * Nc + 8);
        }
        CP_COMMIT();
    }

    for (int kt = 0; kt < nk; kt++) {
        CP_WAIT2();
        __syncthreads();
        if (kt + 3 < nk) {
            int s = (kt + 3) & 3, k0 = (kt + 3) * 16;
            cp16(&As[s][ar * LDA_G + ac], pA + k0);
            if (loadB) {
                cp16(&Bs[s][brow * LDB_G + bn0], pB + (size_t)k0 * Nc);
                cp16(&Bs[s][brow * LDB_G + bn0 + 8], pB + (size_t)k0 * Nc + 8);
            }
        }
        CP_COMMIT();

        int st = kt & 3;
        unsigned af[4][4], bfr[2][4];
#pragma unroll
        for (int mf = 0; mf < 4; mf++) {
            int row = wm + 16 * mf + (sel & 1) * 8 + l7;
            int col = (sel >> 1) * 8;
            ldsm4(af[mf], &As[st][row * LDA_G + col]);
        }
#pragma unroll
        for (int p = 0; p < 2; p++) {
            int row = (sel & 1) * 8 + l7;
            int col = wn + p * 16 + (sel >> 1) * 8;
            ldsm4t(bfr[p], &Bs[st][row * LDB_G + col]);
        }
#pragma unroll
        for (int mf = 0; mf < 4; mf++)
#pragma unroll
            for (int nf = 0; nf < 4; nf++)
                mma_f16(acc[mf][nf], af[mf], &bfr[nf >> 1][(nf & 1) * 2]);
    }

    // epilogue
#pragma unroll
    for (int mf = 0; mf < 4; mf++) {
        int row0 = by * 128 + wm + mf * 16 + rg;
#pragma unroll
        for (int nf = 0; nf < 4; nf++) {
            int col = bx * 128 + wn + nf * 8 + 2 * lc;
            float bz0 = bias[col], bz1 = bias[col + 1];
            if (mode == 0) {
                float2 v0, v1;
                v0.x = acc[mf][nf][0] + bz0; v0.y = acc[mf][nf][1] + bz1;
                v1.x = acc[mf][nf][2] + bz0; v1.y = acc[mf][nf][3] + bz1;
                *(float2*)&Cf[(size_t)row0 * Nc + col] = v0;
                *(float2*)&Cf[(size_t)(row0 + 8) * Nc + col] = v1;
            } else {
                float sc = (col < 512) ? QSCALE : 1.f;
                unsigned h0 = pack2h((acc[mf][nf][0] + bz0) * sc, (acc[mf][nf][1] + bz1) * sc);
                unsigned h1 = pack2h((acc[mf][nf][2] + bz0) * sc, (acc[mf][nf][3] + bz1) * sc);
                *(unsigned*)&g_qkvh[(size_t)row0 * QKV_N + col] = h0;
                *(unsigned*)&g_qkvh[(size_t)(row0 + 8) * QKV_N + col] = h1;
            }
        }
    }
}

// ---------------- DCT features + head MLP -> f, coef ----------------
__global__ void prep_kernel(const float* __restrict__ h1_w, const float* __restrict__ h1_b,
                            const float* __restrict__ h2_w, const float* __restrict__ h2_b)
{
    int b = blockIdx.x, tid = threadIdx.x;
    __shared__ float D[32][33], Am[32][33], T[32][33];
    __shared__ float fbuf[1024];
    __shared__ float xa[512], hid[128], red[256];
    __shared__ float s_norm, s_F, s_s2;

    for (int idx = tid; idx < 1024; idx += 256) {
        int k = idx >> 5, n = idx & 31;
        float v;
        if (k == 0) v = sqrtf(1.f / 32.f);
        else v = sqrtf(2.f / 32.f) * cosf(PI_F * (2.f * n + 1.f) * (float)k / 64.f);
        D[k][n] = v;
    }
    for (int idx = tid; idx < 1024; idx += 256)
        Am[idx >> 5][idx & 31] = g_xmean[b * NN + idx];
    xa[tid]       = g_xavg[b * DIMM + tid];
    xa[tid + 256] = g_xavg[b * DIMM + tid + 256];
    __syncthreads();

    for (int idx = tid; idx < 1024; idx += 256) {
        int k = idx >> 5, n = idx & 31;
        float s = 0.f;
#pragma unroll
        for (int m = 0; m < 32; m++) s += D[k][m] * Am[m][n];
        T[k][n] = s;
    }
    __syncthreads();

    float myv[4];
    float sq = 0.f;
#pragma unroll
    for (int u = 0; u < 4; u++) {
        int idx = tid + u * 256;
        int k = idx >> 5, l = idx & 31;
        float s = 0.f;
#pragma unroll
        for (int n = 0; n < 32; n++) s += T[k][n] * D[l][n];
        s = fminf(fmaxf(s, -10.f), 10.f);
        myv[u] = s;
        sq += s * s;
    }
    red[tid] = sq;
    __syncthreads();
    for (int o = 128; o; o >>= 1) { if (tid < o) red[tid] += red[tid + o]; __syncthreads(); }
    if (tid == 0) s_norm = sqrtf(red[0]) + 1e-5f;
    __syncthreads();

    float inv = 1.f / s_norm;
    float sumf = 0.f;
#pragma unroll
    for (int u = 0; u < 4; u++) {
        myv[u] *= inv;
        fbuf[tid + u * 256] = myv[u];
        sumf += myv[u];
    }
    red[tid] = sumf;
    __syncthreads();
    for (int o = 128; o; o >>= 1) { if (tid < o) red[tid] += red[tid + o]; __syncthreads(); }
    if (tid == 0) s_F = red[0];
    __syncthreads();

    {
        int unit = tid & 127, halfsel = tid >> 7;
        int c0 = halfsel * 256;
        float a0 = 0.f, a1 = 0.f, a2 = 0.f, a3 = 0.f;
#pragma unroll 4
        for (int c = c0; c < c0 + 256; c += 4) {
            a0 += xa[c + 0] * h1_w[(c + 0) * 128 + unit];
            a1 += xa[c + 1] * h1_w[(c + 1) * 128 + unit];
            a2 += xa[c + 2] * h1_w[(c + 2) * 128 + unit];
            a3 += xa[c + 3] * h1_w[(c + 3) * 128 + unit];
        }
        red[tid] = (a0 + a1) + (a2 + a3);
    }
    __syncthreads();
    if (tid < 128) hid[tid] = fmaxf(red[tid] + red[tid + 128] + h1_b[tid], 0.f);
    __syncthreads();
    {
        int w = tid >> 5, lane = tid & 31;
        float s = 0.f;
#pragma unroll
        for (int j = 0; j < 4; j++)
            s += hid[lane + 32 * j] * h2_w[(lane + 32 * j) * 8 + w];
#pragma unroll
        for (int o = 16; o; o >>= 1) s += __shfl_xor_sync(0xffffffffu, s, o);
        if (lane == 0) {
            float t = s + h2_b[w];
            red[w] = t * t;
        }
    }
    __syncthreads();
    if (tid == 0)
        s_s2 = red[0] + red[1] + red[2] + red[3] + red[4] + red[5] + red[6] + red[7];
    __syncthreads();

    float s2 = s_s2, F = s_F;
#pragma unroll
    for (int u = 0; u < 4; u++) {
        int idx = tid + u * 256;
        float fv = fbuf[idx];
        g_f[b * NN + idx] = fv;
        float num = s2 * fv;
        g_coef[b * NN + idx] = num / fmaxf(num * F, 1e-5f);
    }
}

// ---------------- FP16 flash attention, Q-tile 128 (8 warps) ----------------
// grid (NN/128, B*H), block 256. Warp w owns q rows qt*128 + w*16 .. +15.
#define LDK_A 72
__global__ __launch_bounds__(256) void attn_tc(const float* __restrict__ freq_w)
{
    __shared__ __half Ks[2][64 * LDK_A];
    __shared__ __half Vs[2][64 * LDK_A];
    __shared__ float fsb[2][64];

    int qt = blockIdx.x, bh = blockIdx.y;
    int b = bh >> 3, h = bh & 7;
    int tid = threadIdx.x, lane = tid & 31, warp = tid >> 5;
    int rg = lane >> 2, lc = lane & 3;
    int q0 = warp * 16;

    float aw = 1.f / (1.f + __expf(-freq_w[0]));
    float one_aw = 1.f - aw;

    unsigned qa[4][4];
    {
        const __half* qp0 = g_qkvh + (size_t)(b * NN + qt * 128 + q0 + rg) * QKV_N + h * 64;
        const __half* qp1 = qp0 + (size_t)8 * QKV_N;
#pragma unroll
        for (int ds = 0; ds < 4; ds++) {
            qa[ds][0] = *(const unsigned*)(qp0 + 16 * ds + 2 * lc);
            qa[ds][1] = *(const unsigned*)(qp1 + 16 * ds + 2 * lc);
            qa[ds][2] = *(const unsigned*)(qp0 + 16 * ds + 2 * lc + 8);
            qa[ds][3] = *(const unsigned*)(qp1 + 16 * ds + 2 * lc + 8);
        }
    }
    float coef0 = g_coef[b * NN + qt * 128 + q0 + rg];
    float coef1 = g_coef[b * NN + qt * 128 + q0 + rg + 8];

    float m0 = -1e30f, m1 = -1e30f, l0 = 0.f, l1 = 0.f;
    float o[8][4];
#pragma unroll
    for (int nf = 0; nf < 8; nf++)
#pragma unroll
        for (int t = 0; t < 4; t++) o[nf][t] = 0.f;

    // tile loader: 256 threads, K/V rows 64, 4 chunks16 per row each
    int lr = tid >> 2, lq = tid & 3;
    const __half* kb = g_qkvh + (size_t)(b * NN + lr) * QKV_N + 512 + h * 64 + lq * 16;

    {
        cp16(&Ks[0][lr * LDK_A + lq * 16], kb);
        cp16(&Ks[0][lr * LDK_A + lq * 16 + 8], kb + 8);
        cp16(&Vs[0][lr * LDK_A + lq * 16], kb + 512);
        cp16(&Vs[0][lr * LDK_A + lq * 16 + 8], kb + 520);
        if (tid < 16) cp16(&fsb[0][tid * 4], g_f + b * NN + tid * 4);
        CP_COMMIT();
    }

    int sel = lane >> 3, l7 = lane & 7;

    for (int kt = 0; kt < 16; kt++) {
        int st = kt & 1;
        if (kt + 1 < 16) {
            const __half* ks = kb + (size_t)(kt + 1) * 64 * QKV_N;
            int sn = st ^ 1;
            cp16(&Ks[sn][lr * LDK_A + lq * 16], ks);
            cp16(&Ks[sn][lr * LDK_A + lq * 16 + 8], ks + 8);
            cp16(&Vs[sn][lr * LDK_A + lq * 16], ks + 512);
            cp16(&Vs[sn][lr * LDK_A + lq * 16 + 8], ks + 520);
            if (tid < 16) cp16(&fsb[sn][tid * 4], g_f + b * NN + (kt + 1) * 64 + tid * 4);
            CP_COMMIT();
            CP_WAIT1();
        } else {
            CP_WAIT0();
        }
        __syncthreads();

        float sf[8][4];
#pragma unroll
        for (int nf = 0; nf < 8; nf++)
#pragma unroll
            for (int t = 0; t < 4; t++) sf[nf][t] = 0.f;
#pragma unroll
        for (int ds = 0; ds < 4; ds++) {
            int d0 = 16 * ds;
#pragma unroll
            for (int p = 0; p < 4; p++) {
                unsigned bfr[4];
                int row = p * 16 + (sel >> 1) * 8 + l7;
                int col = d0 + (sel & 1) * 8;
                ldsm4(bfr, &Ks[st][row * LDK_A + col]);
                mma_f16(sf[2 * p],     qa[ds], &bfr[0]);
                mma_f16(sf[2 * p + 1], qa[ds], &bfr[2]);
            }
        }

#pragma unroll
        for (int nf = 0; nf < 8; nf++) {
            float f0v = fsb[st][8 * nf + 2 * lc], f1v = fsb[st][8 * nf + 2 * lc + 1];
            float fa;
            fa = fminf(fmaxf(coef0 * f0v, 0.f), 1.f); sf[nf][0] = one_aw * sf[nf][0] + aw * fa;
            fa = fminf(fmaxf(coef0 * f1v, 0.f), 1.f); sf[nf][1] = one_aw * sf[nf][1] + aw * fa;
            fa = fminf(fmaxf(coef1 * f0v, 0.f), 1.f); sf[nf][2] = one_aw * sf[nf][2] + aw * fa;
            fa = fminf(fmaxf(coef1 * f1v, 0.f), 1.f); sf[nf][3] = one_aw * sf[nf][3] + aw * fa;
        }

        float rm0 = -1e30f, rm1 = -1e30f;
#pragma unroll
        for (int nf = 0; nf < 8; nf++) {
            rm0 = fmaxf(rm0, fmaxf(sf[nf][0], sf[nf][1]));
            rm1 = fmaxf(rm1, fmaxf(sf[nf][2], sf[nf][3]));
        }
        rm0 = fmaxf(rm0, __shfl_xor_sync(0xffffffffu, rm0, 1));
        rm0 = fmaxf(rm0, __shfl_xor_sync(0xffffffffu, rm0, 2));
        rm1 = fmaxf(rm1, __shfl_xor_sync(0xffffffffu, rm1, 1));
        rm1 = fmaxf(rm1, __shfl_xor_sync(0xffffffffu, rm1, 2));
        float mn0 = fmaxf(m0, rm0), mn1 = fmaxf(m1, rm1);
        float corr0 = __expf(m0 - mn0), corr1 = __expf(m1 - mn1);
        m0 = mn0; m1 = mn1;
        float rs0 = 0.f, rs1 = 0.f;
#pragma unroll
        for (int nf = 0; nf < 8; nf++) {
            sf[nf][0] = __expf(sf[nf][0] - m0); rs0 += sf[nf][0];
            sf[nf][1] = __expf(sf[nf][1] - m0); rs0 += sf[nf][1];
            sf[nf][2] = __expf(sf[nf][2] - m1); rs1 += sf[nf][2];
            sf[nf][3] = __expf(sf[nf][3] - m1); rs1 += sf[nf][3];
        }
        rs0 += __shfl_xor_sync(0xffffffffu, rs0, 1);
        rs0 += __shfl_xor_sync(0xffffffffu, rs0, 2);
        rs1 += __shfl_xor_sync(0xffffffffu, rs1, 1);
        rs1 += __shfl_xor_sync(0xffffffffu, rs1, 2);
        l0 = l0 * corr0 + rs0;
        l1 = l1 * corr1 + rs1;
#pragma unroll
        for (int nf = 0; nf < 8; nf++) {
            o[nf][0] *= corr0; o[nf][1] *= corr0;
            o[nf][2] *= corr1; o[nf][3] *= corr1;
        }

#pragma unroll
        for (int j = 0; j < 4; j++) {
            unsigned pa[4];
            pa[0] = pack2h(sf[2*j][0],   sf[2*j][1]);
            pa[1] = pack2h(sf[2*j][2],   sf[2*j][3]);
            pa[2] = pack2h(sf[2*j+1][0], sf[2*j+1][1]);
            pa[3] = pack2h(sf[2*j+1][2], sf[2*j+1][3]);
            int k0 = 16 * j;
#pragma unroll
            for (int p = 0; p < 4; p++) {
                unsigned bfr[4];
                int row = k0 + (sel & 1) * 8 + l7;
                int col = p * 16 + (sel >> 1) * 8;
                ldsm4t(bfr, &Vs[st][row * LDK_A + col]);
                mma_f16(o[2 * p],     pa, &bfr[0]);
                mma_f16(o[2 * p + 1], pa, &bfr[2]);
            }
        }
        __syncthreads();
    }

    float iv0 = 1.f / l0, iv1 = 1.f / l1;
    __half* op0 = g_aoh + (size_t)(b * NN + qt * 128 + q0 + rg) * DIMM + h * 64;
    __half* op1 = op0 + (size_t)8 * DIMM;
#pragma unroll
    for (int nf = 0; nf < 8; nf++) {
        int c = 8 * nf + 2 * lc;
        *(unsigned*)&op0[c] = pack2h(o[nf][0] * iv0, o[nf][1] * iv0);
        *(unsigned*)&op1[c] = pack2h(o[nf][2] * iv1, o[nf][3] * iv1);
    }
}

// ---------------- launch ----------------
extern "C" void kernel_launch(void* const* d_in, const int* in_sizes, int n_in,
                              void* d_out, int out_size)
{
    const float* x      = (const float*)d_in[0];
    const float* qkv_w  = (const float*)d_in[1];
    const float* qkv_b  = (const float*)d_in[2];
    const float* proj_w = (const float*)d_in[3];
    const float* proj_b = (const float*)d_in[4];
    const float* h1_w   = (const float*)d_in[5];
    const float* h1_b   = (const float*)d_in[6];
    const float* h2_w   = (const float*)d_in[7];
    const float* h2_b   = (const float*)d_in[8];
    const float* freq_w = (const float*)d_in[9];
    float* out = (float*)d_out;

    convx_kernel<<<M_ROWS / 8, 256>>>(x);
    convw_kernel<<<1024, 256>>>(qkv_w, proj_w);
    colmean_kernel<<<dim3(BB, DIMM / 128), 128>>>(x);
    hgemm<<<dim3(QKV_N / 128, M_ROWS / 128), 256>>>(qkv_b, nullptr, QKV_N, DIMM, 1);
    prep_kernel<<<BB, 256>>>(h1_w, h1_b, h2_w, h2_b);
    attn_tc<<<dim3(NN / 128, BB * HH), 256>>>(freq_w);
    hgemm<<<dim3(DIMM / 128, M_ROWS / 128), 256>>>(proj_b, out, DIMM, DIMM, 0);
}